// round 13
// baseline (speedup 1.0000x reference)
#include <cuda_runtime.h>
#include <cuda_bf16.h>
#include <cstdint>

#define NN   50000
#define EE   800000
#define IN_F 128
#define EIN_F 64
#define HID  256
#define OUTF 256
#define LNUM 3
#define HH   4
#define DD   64

// ---------------- device scratch (no cudaMalloc allowed) ----------------
__device__ __align__(16) float g_X[NN * HID];
__device__ __align__(16) float g_FEAT[NN * HID];
__device__ __align__(16) float g_el[NN * HH];
__device__ __align__(16) float g_er[NN * HH];
__device__ __align__(16) float g_ee[(size_t)EE * LNUM * HH];
__device__ __align__(16) float g_alpha[(size_t)EE * HH];
__device__ int g_off[NN + 1];
__device__ int g_cursor[NN];
__device__ int g_csr_src[EE];
__device__ int g_csr_eid[EE];
__device__ float g_V[LNUM * HID * HH];
__device__ float g_U[LNUM * EIN_F * HH];
__device__ float g_eebias[LNUM * HH];
// pre-split bf16 operands (hi/lo), packed 2 per u32
__device__ __align__(16) uint32_t g_hh[NN * IN_F / 2];   // h split
__device__ __align__(16) uint32_t g_hl[NN * IN_F / 2];
__device__ __align__(16) uint32_t g_Xh[NN * HID / 2];    // X split
__device__ __align__(16) uint32_t g_Xl[NN * HID / 2];
// weights pre-transposed+split: enc (256x64) then Wn[0..2] & out (256x128 each)
#define BT_ENC 0
#define BT_WN(l) (16384 + (l) * 32768)
#define BT_OUT (16384 + 3 * 32768)
__device__ __align__(16) uint32_t g_BTh[16384 + 4 * 32768];
__device__ __align__(16) uint32_t g_BTl[16384 + 4 * 32768];

static inline int divup(int a, int b) { return (a + b - 1) / b; }

// ---------------- bf16 helpers ----------------
__device__ __forceinline__ uint32_t pack2(__nv_bfloat16 a, __nv_bfloat16 b) {
    __nv_bfloat162 t;
    t.x = a; t.y = b;
    return *reinterpret_cast<uint32_t*>(&t);
}
__device__ __forceinline__ void cvt_pair(float a, float b, uint32_t& hi, uint32_t& lo) {
    __nv_bfloat16 ha = __float2bfloat16(a), hb = __float2bfloat16(b);
    hi = pack2(ha, hb);
    float ra = a - __bfloat162float(ha);
    float rb = b - __bfloat162float(hb);
    lo = pack2(__float2bfloat16(ra), __float2bfloat16(rb));
}
__device__ __forceinline__ void mma_bf16(float* c, const uint32_t* a, const uint32_t* b) {
    asm volatile(
        "mma.sync.aligned.m16n8k16.row.col.f32.bf16.bf16.f32 "
        "{%0,%1,%2,%3}, {%4,%5,%6,%7}, {%8,%9}, {%0,%1,%2,%3};"
        : "+f"(c[0]), "+f"(c[1]), "+f"(c[2]), "+f"(c[3])
        : "r"(a[0]), "r"(a[1]), "r"(a[2]), "r"(a[3]), "r"(b[0]), "r"(b[1]));
}
__device__ __forceinline__ uint32_t smem_u32(const void* p) {
    uint32_t a;
    asm("{ .reg .u64 t; cvta.to.shared.u64 t, %1; cvt.u32.u64 %0, t; }" : "=r"(a) : "l"(p));
    return a;
}
__device__ __forceinline__ void ldsm_x4(uint32_t* r, uint32_t a) {
    asm volatile("ldmatrix.sync.aligned.m8n8.x4.shared.b16 {%0,%1,%2,%3}, [%4];"
                 : "=r"(r[0]), "=r"(r[1]), "=r"(r[2]), "=r"(r[3]) : "r"(a));
}

// ---------------- fused front 1 ----------------
// [0,196) cursor zero; [196,208) V; [208,240) enc T; [240,496) Wn/out T;
// [496,3621) h split -> g_hh/g_hl
__global__ __launch_bounds__(256) void k_front1(const float* __restrict__ We,
                                                const float* __restrict__ ae,
                                                const float* __restrict__ enc_w,
                                                const float* __restrict__ Wn,
                                                const float* __restrict__ out_w,
                                                const float* __restrict__ h) {
    __shared__ float t[32][33];
    const int b = blockIdx.x;
    const int tid = threadIdx.x;
    if (b < 196) {
        int i = b * 256 + tid;
        if (i < NN) g_cursor[i] = 0;
        return;
    }
    if (b < 208) {
        int idx = (b - 196) * 256 + tid;
        if (idx < LNUM * HID * HH) {
            int hh = idx & 3;
            int hid = (idx >> 2) & (HID - 1);
            int l = idx >> 10;
            const float* wp = We + ((size_t)(l * HID + hid)) * HID + hh * DD;
            const float* ap = ae + (l * HH + hh) * DD;
            float s = 0.f;
#pragma unroll 8
            for (int d = 0; d < DD; d++) s += wp[d] * ap[d];
            g_V[idx] = s;
        }
        return;
    }
    if (b >= 496) {
        // h split: one thread handles 8 floats
        int j = (b - 496) * 256 + tid;       // < 800000
        size_t o8 = (size_t)j * 8;
        float4 v0 = *(const float4*)(h + o8);
        float4 v1 = *(const float4*)(h + o8 + 4);
        uint32_t h0, l0, h1, l1, h2, l2, h3, l3;
        cvt_pair(v0.x, v0.y, h0, l0);
        cvt_pair(v0.z, v0.w, h1, l1);
        cvt_pair(v1.x, v1.y, h2, l2);
        cvt_pair(v1.z, v1.w, h3, l3);
        *(uint4*)(g_hh + (o8 >> 1)) = make_uint4(h0, h1, h2, h3);
        *(uint4*)(g_hl + (o8 >> 1)) = make_uint4(l0, l1, l2, l3);
        return;
    }
    // transpose section
    const float* src;
    int n0, k0, K, bto;
    if (b < 240) {
        const int b2 = b - 208;
        src = enc_w; K = IN_F; bto = BT_ENC;
        n0 = (b2 & 7) * 32;
        k0 = (b2 >> 3) * 32;
    } else {
        const int b3 = b - 240;
        const int w = b3 >> 6;
        src = (w < 3) ? (Wn + (size_t)w * HID * HID) : out_w;
        K = HID; bto = 16384 + w * 32768;
        const int b4 = b3 & 63;
        n0 = (b4 & 7) * 32;
        k0 = (b4 >> 3) * 32;
    }
    const int tx = tid & 31, ty = tid >> 5;
#pragma unroll
    for (int i = 0; i < 32; i += 8)
        t[ty + i][tx] = src[(size_t)(k0 + ty + i) * HID + n0 + tx];
    __syncthreads();
    const int Kh = K >> 1;
#pragma unroll
    for (int it = 0; it < 2; it++) {
        int j = tid + it * 256;
        int n = j >> 4, c = j & 15;
        float ve = t[2 * c][n], vo = t[2 * c + 1][n];
        uint32_t hi, lo;
        cvt_pair(ve, vo, hi, lo);
        g_BTh[bto + (size_t)(n0 + n) * Kh + (k0 >> 1) + c] = hi;
        g_BTl[bto + (size_t)(n0 + n) * Kh + (k0 >> 1) + c] = lo;
    }
}

// ---------------- fused front 2: hist + fold-U ----------------------------------
__global__ __launch_bounds__(256) void k_front2(const int* __restrict__ dst,
                                                const float* __restrict__ eenc_w,
                                                const float* __restrict__ eenc_b) {
    const int b = blockIdx.x;
    const int tid = threadIdx.x;
    if (b < 3125) {
        int i = b * 256 + tid;
        if (i < EE) atomicAdd(&g_cursor[dst[i]], 1);
    } else {
        int idx = (b - 3125) * 256 + tid;
        if (idx < LNUM * EIN_F * HH) {
            int h = idx & 3;
            int k = (idx >> 2) & 63;
            int l = idx >> 8;
            const float* wp = eenc_w + k * HID;
            float s = 0.f;
#pragma unroll 8
            for (int hid = 0; hid < HID; hid++) s += wp[hid] * g_V[(l * HID + hid) * HH + h];
            g_U[idx] = s;
        } else if (idx < LNUM * EIN_F * HH + LNUM * HH) {
            int j = idx - LNUM * EIN_F * HH;
            int l = j >> 2, h = j & 3;
            float s = 0.f;
            for (int hid = 0; hid < HID; hid++) s += eenc_b[hid] * g_V[(l * HID + hid) * HH + h];
            g_eebias[j] = s;
        }
    }
}

// ---------------- scan (also initializes cursor) --------------------------------
__global__ void k_scan() {
    __shared__ int sh[1024];
    const int t = threadIdx.x;
    const int chunk = (NN + 1023) / 1024;
    const int start = t * chunk;
    const int end = min(start + chunk, NN);
    int s = 0;
    for (int i = start; i < end; i++) s += g_cursor[i];
    sh[t] = s;
    __syncthreads();
    for (int o = 1; o < 1024; o <<= 1) {
        int v = (t >= o) ? sh[t - o] : 0;
        __syncthreads();
        sh[t] += v;
        __syncthreads();
    }
    int run = sh[t] - s;
    for (int i = start; i < end; i++) {
        int d = g_cursor[i];
        g_off[i] = run;
        g_cursor[i] = run;
        run += d;
    }
    if (t == 1023) g_off[NN] = sh[1023];
}

// ---------------- fused: scatter + ee GEMM --------------------------------------
__global__ __launch_bounds__(256) void k_scatter_ee(const int* __restrict__ src,
                                                    const int* __restrict__ dst,
                                                    const float* __restrict__ efeat) {
    __shared__ float fs[128 * 65];
    __shared__ float us[64 * 12];
    const int b = blockIdx.x;
    const int tid = threadIdx.x;
    if (b < 3125) {
        int i = b * 256 + tid;
        if (i < EE) {
            int p = atomicAdd(&g_cursor[dst[i]], 1);
            g_csr_src[p] = src[i];
            g_csr_eid[p] = i;
        }
    } else {
        const int e0 = (b - 3125) * 128;
        for (int i = tid; i < 128 * 64; i += 256) {
            int e = i >> 6, k = i & 63;
            fs[e * 65 + k] = efeat[(size_t)(e0 + e) * 64 + k];
        }
        for (int i = tid; i < LNUM * EIN_F * HH; i += 256) {
            int h = i & 3, k = (i >> 2) & 63, l = i >> 8;
            us[k * 12 + l * 4 + h] = g_U[i];
        }
        __syncthreads();
#pragma unroll
        for (int p0 = 0; p0 < 6; p0++) {
            int p = p0 * 256 + tid;
            int e = p & 127, out = p >> 7;
            const float* fp = &fs[e * 65];
            float acc = 0.f;
#pragma unroll
            for (int k = 0; k < 64; k++) acc += fp[k] * us[k * 12 + out];
            g_ee[(size_t)(e0 + e) * 12 + out] = acc + g_eebias[out];
        }
    }
}

// ---------------- bf16 3-split mma.sync GEMM, pre-split A, 128x64 tile ----------
// A given as packed bf16 hi/lo (2 per u32). No conversion in the mainloop.
// When alp != null: zero + accumulate el/er. When Xh != null: also emit C split.
#define SST 20
#define BUFU 7680
__global__ __launch_bounds__(256, 2) void k_gemm_bf16(
    const uint32_t* __restrict__ Ah, const uint32_t* __restrict__ Al,
    const uint32_t* __restrict__ BTh, const uint32_t* __restrict__ BTl,
    const float* __restrict__ bias, float* __restrict__ C, int M, int K,
    const float* __restrict__ alp, const float* __restrict__ arp,
    uint32_t* __restrict__ Xh, uint32_t* __restrict__ Xl) {
    extern __shared__ uint32_t smu[];

    const int tid = threadIdx.x;
    const int wid = tid >> 5;
    const int lane = tid & 31;
    const int g = lane >> 2;
    const int tg = lane & 3;
    const int m0 = blockIdx.x * 128;
    const int col0 = blockIdx.y * 64;
    const int wm = wid >> 1;
    const int wn = wid & 1;
    const int Kh = K >> 1;
    const int nchunk = K >> 5;

    if (alp) {
        const int h = blockIdx.y;
        if (tid < 128) {
            int r = m0 + tid;
            if (r < M) g_el[r * 4 + h] = 0.f;
        } else {
            int r = m0 + tid - 128;
            if (r < M) g_er[r * 4 + h] = 0.f;
        }
    }

    const int fAr = tid >> 2, fAq = (tid & 3) << 2;   // A: rows 0..63 (+t*64), 16 u32/row
    const int fBr = tid >> 2, fBq = (tid & 3) << 2;   // B: 64 rows

    const uint32_t smem_base = smem_u32(smu);
    const int l15 = lane & 15;
    const uint32_t aRowOff = (uint32_t)(((wm * 32 + l15) * SST + ((lane >> 4) & 1) * 4) * 4);
    const int bm = lane >> 3, br = lane & 7;
    const uint32_t bX4Off = (uint32_t)(((wn * 32 + (bm >> 1) * 8 + br) * SST + (bm & 1) * 4) * 4);

    float acc[2][4][4];
#pragma unroll
    for (int i = 0; i < 2; i++)
#pragma unroll
        for (int j = 0; j < 4; j++)
#pragma unroll
            for (int q = 0; q < 4; q++) acc[i][j][q] = 0.f;

    uint4 stAh[2], stAl[2], stBh, stBl;

#define LOADG(cc) do {                                                        \
    const int kc0h = (cc) << 4;                                               \
    _Pragma("unroll")                                                         \
    for (int t = 0; t < 2; t++) {                                             \
        int gr = min(m0 + fAr + t * 64, M - 1);                               \
        size_t o = (size_t)gr * Kh + kc0h + fAq;                              \
        stAh[t] = *(const uint4*)(Ah + o);                                    \
        stAl[t] = *(const uint4*)(Al + o);                                    \
    }                                                                         \
    {                                                                         \
        size_t o = (size_t)(col0 + fBr) * Kh + kc0h + fBq;                    \
        stBh = *(const uint4*)(BTh + o);                                      \
        stBl = *(const uint4*)(BTl + o);                                      \
    }                                                                         \
} while (0)

#define STOREB(buf) do {                                                      \
    uint32_t* bA = smu + (buf)*BUFU;                                          \
    _Pragma("unroll")                                                         \
    for (int t = 0; t < 2; t++) {                                             \
        int so = (fAr + t * 64) * SST + fAq;                                  \
        *(uint4*)(bA + so) = stAh[t];                                         \
        *(uint4*)(bA + 2560 + so) = stAl[t];                                  \
    }                                                                         \
    {                                                                         \
        int so = fBr * SST + fBq;                                             \
        *(uint4*)(bA + 5120 + so) = stBh;                                     \
        *(uint4*)(bA + 6400 + so) = stBl;                                     \
    }                                                                         \
} while (0)

    LOADG(0);
    STOREB(0);
    __syncthreads();

    for (int c = 0; c < nchunk; c++) {
        const int cur = c & 1;
        const bool more = (c + 1 < nchunk);
        if (more) LOADG(c + 1);

        const uint32_t bufB = smem_base + (uint32_t)(cur * BUFU * 4);
#pragma unroll
        for (int ks = 0; ks < 2; ks++) {
            uint32_t ah[2][4], al_[2][4], bh[4][2], bl[4][2];
            const uint32_t aH = bufB + aRowOff + ks * 32;
            const uint32_t bH = bufB + 5120 * 4 + bX4Off + ks * 32;
#pragma unroll
            for (int ma = 0; ma < 2; ma++) {
                ldsm_x4(ah[ma], aH + ma * (16 * SST * 4));
                ldsm_x4(al_[ma], aH + 2560 * 4 + ma * (16 * SST * 4));
            }
#pragma unroll
            for (int p = 0; p < 2; p++) {
                uint32_t bt[4];
                ldsm_x4(bt, bH + p * (16 * SST * 4));
                bh[2 * p][0] = bt[0]; bh[2 * p][1] = bt[1];
                bh[2 * p + 1][0] = bt[2]; bh[2 * p + 1][1] = bt[3];
                ldsm_x4(bt, bH + 1280 * 4 + p * (16 * SST * 4));
                bl[2 * p][0] = bt[0]; bl[2 * p][1] = bt[1];
                bl[2 * p + 1][0] = bt[2]; bl[2 * p + 1][1] = bt[3];
            }
#pragma unroll
            for (int ma = 0; ma < 2; ma++)
#pragma unroll
                for (int na = 0; na < 4; na++) mma_bf16(acc[ma][na], ah[ma], bh[na]);
#pragma unroll
            for (int ma = 0; ma < 2; ma++)
#pragma unroll
                for (int na = 0; na < 4; na++) mma_bf16(acc[ma][na], ah[ma], bl[na]);
#pragma unroll
            for (int ma = 0; ma < 2; ma++)
#pragma unroll
                for (int na = 0; na < 4; na++) mma_bf16(acc[ma][na], al_[ma], bh[na]);
        }
        if (more) {
            STOREB(1 - cur);
            __syncthreads();
        }
    }

    // store C (+bias), optionally emit split form for the next GEMM's A
#pragma unroll
    for (int ma = 0; ma < 2; ma++) {
        const int r0 = m0 + wm * 32 + ma * 16 + g;
        const int r1 = r0 + 8;
#pragma unroll
        for (int na = 0; na < 4; na++) {
            const int cc = col0 + wn * 32 + na * 8 + 2 * tg;
            float b0 = 0.f, b1 = 0.f;
            if (bias) { b0 = __ldg(bias + cc); b1 = __ldg(bias + cc + 1); }
            if (r0 < M) {
                float2 o = make_float2(acc[ma][na][0] + b0, acc[ma][na][1] + b1);
                *(float2*)(C + (size_t)r0 * 256 + cc) = o;
                if (Xh) {
                    uint32_t hi, lo;
                    cvt_pair(o.x, o.y, hi, lo);
                    Xh[(size_t)r0 * 128 + (cc >> 1)] = hi;
                    Xl[(size_t)r0 * 128 + (cc >> 1)] = lo;
                }
            }
            if (r1 < M) {
                float2 o = make_float2(acc[ma][na][2] + b0, acc[ma][na][3] + b1);
                *(float2*)(C + (size_t)r1 * 256 + cc) = o;
                if (Xh) {
                    uint32_t hi, lo;
                    cvt_pair(o.x, o.y, hi, lo);
                    Xh[(size_t)r1 * 128 + (cc >> 1)] = hi;
                    Xl[(size_t)r1 * 128 + (cc >> 1)] = lo;
                }
            }
        }
    }

    // fused el/er: CTA's 64 cols = one head
    if (alp) {
        const int h = blockIdx.y;
        float av0[4], av1[4], rv0[4], rv1[4];
#pragma unroll
        for (int na = 0; na < 4; na++) {
            const int d = wn * 32 + na * 8 + 2 * tg;
            av0[na] = __ldg(alp + h * DD + d);
            av1[na] = __ldg(alp + h * DD + d + 1);
            rv0[na] = __ldg(arp + h * DD + d);
            rv1[na] = __ldg(arp + h * DD + d + 1);
        }
#pragma unroll
        for (int ma = 0; ma < 2; ma++) {
            float pel0 = 0.f, pel1 = 0.f, per0 = 0.f, per1 = 0.f;
#pragma unroll
            for (int na = 0; na < 4; na++) {
                pel0 += acc[ma][na][0] * av0[na] + acc[ma][na][1] * av1[na];
                pel1 += acc[ma][na][2] * av0[na] + acc[ma][na][3] * av1[na];
                per0 += acc[ma][na][0] * rv0[na] + acc[ma][na][1] * rv1[na];
                per1 += acc[ma][na][2] * rv0[na] + acc[ma][na][3] * rv1[na];
            }
#pragma unroll
            for (int o = 1; o < 4; o <<= 1) {
                pel0 += __shfl_xor_sync(0xffffffffu, pel0, o);
                pel1 += __shfl_xor_sync(0xffffffffu, pel1, o);
                per0 += __shfl_xor_sync(0xffffffffu, per0, o);
                per1 += __shfl_xor_sync(0xffffffffu, per1, o);
            }
            if (tg == 0) {
                const int r0 = m0 + wm * 32 + ma * 16 + g;
                const int r1 = r0 + 8;
                if (r0 < M) {
                    atomicAdd(&g_el[r0 * 4 + h], pel0);
                    atomicAdd(&g_er[r0 * 4 + h], per0);
                }
                if (r1 < M) {
                    atomicAdd(&g_el[r1 * 4 + h], pel1);
                    atomicAdd(&g_er[r1 * 4 + h], per1);
                }
            }
        }
    }
#undef LOADG
#undef STOREB
}

// ---------------- per-dst-node: softmax + aggregate + LN (R8 two-pass) ----------
__device__ __forceinline__ float lrelu(float e) { return e > 0.f ? e : 0.2f * e; }

__global__ __launch_bounds__(256) void k_edge(int l,
                                              const float* __restrict__ ln_g,
                                              const float* __restrict__ ln_b) {
    const int lane = threadIdx.x & 31;
    const int n = blockIdx.x * 8 + (threadIdx.x >> 5);
    if (n >= NN) return;
    const int beg = g_off[n], end = g_off[n + 1];
    const float4 er4 = *(const float4*)&g_er[n * 4];

    float s0 = 0.f, s1 = 0.f, s2 = 0.f, s3 = 0.f;
    for (int i = beg + lane; i < end; i += 32) {
        const int s = g_csr_src[i];
        const int eid = g_csr_eid[i];
        const float4 el4 = *(const float4*)&g_el[s * 4];
        const float4 ee4 = *(const float4*)&g_ee[(size_t)eid * 12 + l * 4];
        float4 e;
        e.x = __expf(lrelu(el4.x + er4.x + ee4.x)); s0 += e.x;
        e.y = __expf(lrelu(el4.y + er4.y + ee4.y)); s1 += e.y;
        e.z = __expf(lrelu(el4.z + er4.z + ee4.z)); s2 += e.z;
        e.w = __expf(lrelu(el4.w + er4.w + ee4.w)); s3 += e.w;
        *(float4*)&g_alpha[(size_t)i * 4] = e;
    }
#pragma unroll
    for (int o = 16; o; o >>= 1) {
        s0 += __shfl_xor_sync(0xffffffffu, s0, o);
        s1 += __shfl_xor_sync(0xffffffffu, s1, o);
        s2 += __shfl_xor_sync(0xffffffffu, s2, o);
        s3 += __shfl_xor_sync(0xffffffffu, s3, o);
    }
    __syncwarp();
    const int myhead = lane >> 3;
    const float rs_my = (myhead == 0) ? 1.f / s0 : (myhead == 1) ? 1.f / s1
                      : (myhead == 2) ? 1.f / s2 : 1.f / s3;

    float a0 = 0.f, a1 = 0.f, a2 = 0.f, a3 = 0.f, a4 = 0.f, a5 = 0.f, a6 = 0.f, a7 = 0.f;
    int i = beg;
    for (; i + 4 <= end; i += 4) {
        int sx[4];
        float aw[4];
        const float4* fr[4];
#pragma unroll
        for (int u = 0; u < 4; u++) {
            sx[u] = g_csr_src[i + u];
            const float4 alv = *(const float4*)&g_alpha[(size_t)(i + u) * 4];
            aw[u] = ((myhead == 0) ? alv.x : (myhead == 1) ? alv.y
                    : (myhead == 2) ? alv.z : alv.w) * rs_my;
            fr[u] = (const float4*)(g_FEAT + (size_t)sx[u] * HID + lane * 8);
        }
        float4 f0[4], f1[4];
#pragma unroll
        for (int u = 0; u < 4; u++) { f0[u] = __ldg(fr[u]); f1[u] = __ldg(fr[u] + 1); }
#pragma unroll
        for (int u = 0; u < 4; u++) {
            const float a = aw[u];
            a0 += a * f0[u].x; a1 += a * f0[u].y; a2 += a * f0[u].z; a3 += a * f0[u].w;
            a4 += a * f1[u].x; a5 += a * f1[u].y; a6 += a * f1[u].z; a7 += a * f1[u].w;
        }
    }
    for (; i < end; i++) {
        const int sA = g_csr_src[i];
        const float4 alv = *(const float4*)&g_alpha[(size_t)i * 4];
        const float a = ((myhead == 0) ? alv.x : (myhead == 1) ? alv.y
                        : (myhead == 2) ? alv.z : alv.w) * rs_my;
        const float4* frA = (const float4*)(g_FEAT + (size_t)sA * HID + lane * 8);
        const float4 fA0 = __ldg(frA), fA1 = __ldg(frA + 1);
        a0 += a * fA0.x; a1 += a * fA0.y; a2 += a * fA0.z; a3 += a * fA0.w;
        a4 += a * fA1.x; a5 += a * fA1.y; a6 += a * fA1.z; a7 += a * fA1.w;
    }

    const float4 r0 = *(const float4*)(g_X + (size_t)n * HID + lane * 8);
    const float4 r1 = *(const float4*)(g_X + (size_t)n * HID + lane * 8 + 4);
    float y[8];
    y[0] = fmaxf(a0, 0.f) + r0.x; y[1] = fmaxf(a1, 0.f) + r0.y;
    y[2] = fmaxf(a2, 0.f) + r0.z; y[3] = fmaxf(a3, 0.f) + r0.w;
    y[4] = fmaxf(a4, 0.f) + r1.x; y[5] = fmaxf(a5, 0.f) + r1.y;
    y[6] = fmaxf(a6, 0.f) + r1.z; y[7] = fmaxf(a7, 0.f) + r1.w;
    float sum = 0.f;
#pragma unroll
    for (int j = 0; j < 8; j++) sum += y[j];
#pragma unroll
    for (int o = 16; o; o >>= 1) sum += __shfl_xor_sync(0xffffffffu, sum, o);
    const float mu = sum * (1.f / 256.f);
    float vs = 0.f;
#pragma unroll
    for (int j = 0; j < 8; j++) { float d = y[j] - mu; vs += d * d; }
#pragma unroll
    for (int o = 16; o; o >>= 1) vs += __shfl_xor_sync(0xffffffffu, vs, o);
    const float rstd = rsqrtf(vs * (1.f / 256.f) + 1e-5f);
    const float* gp = ln_g + lane * 8;
    const float* bp = ln_b + lane * 8;
    float4 o0, o1;
    o0.x = (y[0] - mu) * rstd * gp[0] + bp[0];
    o0.y = (y[1] - mu) * rstd * gp[1] + bp[1];
    o0.z = (y[2] - mu) * rstd * gp[2] + bp[2];
    o0.w = (y[3] - mu) * rstd * gp[3] + bp[3];
    o1.x = (y[4] - mu) * rstd * gp[4] + bp[4];
    o1.y = (y[5] - mu) * rstd * gp[5] + bp[5];
    o1.z = (y[6] - mu) * rstd * gp[6] + bp[6];
    o1.w = (y[7] - mu) * rstd * gp[7] + bp[7];
    *(float4*)(g_X + (size_t)n * HID + lane * 8) = o0;
    *(float4*)(g_X + (size_t)n * HID + lane * 8 + 4) = o1;

    // emit split form for the next GEMM's A operand
    uint32_t xh0, xl0, xh1, xl1, xh2, xl2, xh3, xl3;
    cvt_pair(o0.x, o0.y, xh0, xl0);
    cvt_pair(o0.z, o0.w, xh1, xl1);
    cvt_pair(o1.x, o1.y, xh2, xl2);
    cvt_pair(o1.z, o1.w, xh3, xl3);
    *(uint4*)(g_Xh + (size_t)n * 128 + lane * 4) = make_uint4(xh0, xh1, xh2, xh3);
    *(uint4*)(g_Xl + (size_t)n * 128 + lane * 4) = make_uint4(xl0, xl1, xl2, xl3);
}

// ---------------- launch ----------------
extern "C" void kernel_launch(void* const* d_in, const int* in_sizes, int n_in,
                              void* d_out, int out_size) {
    const float* h      = (const float*)d_in[0];
    const float* efeat  = (const float*)d_in[1];
    const int*   src    = (const int*)d_in[2];
    const int*   dst    = (const int*)d_in[3];
    const float* enc_w  = (const float*)d_in[4];
    const float* enc_b  = (const float*)d_in[5];
    const float* eenc_w = (const float*)d_in[6];
    const float* eenc_b = (const float*)d_in[7];
    const float* Wn     = (const float*)d_in[8];
    const float* We     = (const float*)d_in[9];
    const float* al     = (const float*)d_in[10];
    const float* ar     = (const float*)d_in[11];
    const float* ae     = (const float*)d_in[12];
    const float* ln_g   = (const float*)d_in[13];
    const float* ln_b   = (const float*)d_in[14];
    const float* out_w  = (const float*)d_in[15];
    const float* out_b  = (const float*)d_in[16];
    float* out = (float*)d_out;

    float *X, *FEAT;
    uint32_t *BTh, *BTl, *hh, *hl, *Xh, *Xl;
    cudaGetSymbolAddress((void**)&X, g_X);
    cudaGetSymbolAddress((void**)&FEAT, g_FEAT);
    cudaGetSymbolAddress((void**)&BTh, g_BTh);
    cudaGetSymbolAddress((void**)&BTl, g_BTl);
    cudaGetSymbolAddress((void**)&hh, g_hh);
    cudaGetSymbolAddress((void**)&hl, g_hl);
    cudaGetSymbolAddress((void**)&Xh, g_Xh);
    cudaGetSymbolAddress((void**)&Xl, g_Xl);

    const int DSM = 2 * BUFU * 4;
    cudaFuncSetAttribute(k_gemm_bf16, cudaFuncAttributeMaxDynamicSharedMemorySize, DSM);
    const int MTILES = divup(NN, 128);
    const dim3 ggrid(MTILES, 4);

    k_front1<<<496 + 3125, 256>>>(We, ae, enc_w, Wn, out_w, h);          // 0
    k_front2<<<3129, 256>>>(dst, eenc_w, eenc_b);                        // 1
    k_scan<<<1, 1024>>>();                                               // 2
    k_gemm_bf16<<<ggrid, 256, DSM>>>(hh, hl, BTh + BT_ENC, BTl + BT_ENC, enc_b,
                                     X, NN, IN_F, nullptr, nullptr, Xh, Xl); // 3 <- ncu
    k_scatter_ee<<<3125 + EE / 128, 256>>>(src, dst, efeat);             // 4

    for (int l = 0; l < LNUM; l++) {
        k_gemm_bf16<<<ggrid, 256, DSM>>>(Xh, Xl, BTh + BT_WN(l), BTl + BT_WN(l), nullptr,
                                         FEAT, NN, HID,
                                         al + l * HH * DD, ar + l * HH * DD,
                                         nullptr, nullptr);
        k_edge<<<divup(NN, 8), 256>>>(l, ln_g + l * HID, ln_b + l * HID);
    }

    k_gemm_bf16<<<ggrid, 256, DSM>>>(Xh, Xl, BTh + BT_OUT, BTl + BT_OUT, out_b,
                                     out, NN, HID, nullptr, nullptr, nullptr, nullptr);
}

// round 14
// speedup vs baseline: 1.0454x; 1.0454x over previous
#include <cuda_runtime.h>
#include <cuda_bf16.h>
#include <cstdint>

#define NN   50000
#define EE   800000
#define IN_F 128
#define EIN_F 64
#define HID  256
#define OUTF 256
#define LNUM 3
#define HH   4
#define DD   64

// ---------------- device scratch (no cudaMalloc allowed) ----------------
__device__ __align__(16) float g_X[NN * HID];
__device__ __align__(16) float g_FEAT[NN * HID];
__device__ __align__(16) float g_el[NN * HH];
__device__ __align__(16) float g_er[NN * HH];
__device__ __align__(16) float g_ee[(size_t)EE * LNUM * HH];
__device__ __align__(16) float g_alpha[(size_t)EE * HH];
__device__ int g_off[NN + 1];
__device__ int g_cursor[NN];
__device__ int g_csr_src[EE];
__device__ int g_csr_eid[EE];
__device__ float g_V[LNUM * HID * HH];
__device__ float g_U[LNUM * EIN_F * HH];
__device__ float g_eebias[LNUM * HH];
// weights pre-transposed+split: enc (256x64) then Wn[0..2] & out (256x128 each)
#define BT_ENC 0
#define BT_WN(l) (16384 + (l) * 32768)
#define BT_OUT (16384 + 3 * 32768)
__device__ __align__(16) uint32_t g_BTh[16384 + 4 * 32768];
__device__ __align__(16) uint32_t g_BTl[16384 + 4 * 32768];

static inline int divup(int a, int b) { return (a + b - 1) / b; }

// ---------------- bf16 helpers ----------------
__device__ __forceinline__ uint32_t pack2(__nv_bfloat16 a, __nv_bfloat16 b) {
    __nv_bfloat162 t;
    t.x = a; t.y = b;
    return *reinterpret_cast<uint32_t*>(&t);
}
__device__ __forceinline__ void cvt_pair(float a, float b, uint32_t& hi, uint32_t& lo) {
    __nv_bfloat16 ha = __float2bfloat16(a), hb = __float2bfloat16(b);
    hi = pack2(ha, hb);
    float ra = a - __bfloat162float(ha);
    float rb = b - __bfloat162float(hb);
    lo = pack2(__float2bfloat16(ra), __float2bfloat16(rb));
}
__device__ __forceinline__ void mma_bf16(float* c, const uint32_t* a, const uint32_t* b) {
    asm volatile(
        "mma.sync.aligned.m16n8k16.row.col.f32.bf16.bf16.f32 "
        "{%0,%1,%2,%3}, {%4,%5,%6,%7}, {%8,%9}, {%0,%1,%2,%3};"
        : "+f"(c[0]), "+f"(c[1]), "+f"(c[2]), "+f"(c[3])
        : "r"(a[0]), "r"(a[1]), "r"(a[2]), "r"(a[3]), "r"(b[0]), "r"(b[1]));
}
__device__ __forceinline__ uint32_t smem_u32(const void* p) {
    uint32_t a;
    asm("{ .reg .u64 t; cvta.to.shared.u64 t, %1; cvt.u32.u64 %0, t; }" : "=r"(a) : "l"(p));
    return a;
}
__device__ __forceinline__ void ldsm_x4(uint32_t* r, uint32_t a) {
    asm volatile("ldmatrix.sync.aligned.m8n8.x4.shared.b16 {%0,%1,%2,%3}, [%4];"
                 : "=r"(r[0]), "=r"(r[1]), "=r"(r[2]), "=r"(r[3]) : "r"(a));
}

// ---------------- fused front 1: zero-cursor + fold-V + ALL weight transposes ---
__global__ __launch_bounds__(256) void k_front1(const float* __restrict__ We,
                                                const float* __restrict__ ae,
                                                const float* __restrict__ enc_w,
                                                const float* __restrict__ Wn,
                                                const float* __restrict__ out_w) {
    __shared__ float t[32][33];
    const int b = blockIdx.x;
    const int tid = threadIdx.x;
    if (b < 196) {
        int i = b * 256 + tid;
        if (i < NN) g_cursor[i] = 0;
        return;
    }
    if (b < 208) {
        int idx = (b - 196) * 256 + tid;
        if (idx < LNUM * HID * HH) {
            int h = idx & 3;
            int hid = (idx >> 2) & (HID - 1);
            int l = idx >> 10;
            const float* wp = We + ((size_t)(l * HID + hid)) * HID + h * DD;
            const float* ap = ae + (l * HH + h) * DD;
            float s = 0.f;
#pragma unroll 8
            for (int d = 0; d < DD; d++) s += wp[d] * ap[d];
            g_V[idx] = s;
        }
        return;
    }
    const float* src;
    int n0, k0, K, bto;
    if (b < 240) {
        const int b2 = b - 208;
        src = enc_w; K = IN_F; bto = BT_ENC;
        n0 = (b2 & 7) * 32;
        k0 = (b2 >> 3) * 32;
    } else {
        const int b3 = b - 240;
        const int w = b3 >> 6;
        src = (w < 3) ? (Wn + (size_t)w * HID * HID) : out_w;
        K = HID; bto = 16384 + w * 32768;
        const int b4 = b3 & 63;
        n0 = (b4 & 7) * 32;
        k0 = (b4 >> 3) * 32;
    }
    const int tx = tid & 31, ty = tid >> 5;
#pragma unroll
    for (int i = 0; i < 32; i += 8)
        t[ty + i][tx] = src[(size_t)(k0 + ty + i) * HID + n0 + tx];
    __syncthreads();
    const int Kh = K >> 1;
#pragma unroll
    for (int it = 0; it < 2; it++) {
        int j = tid + it * 256;
        int n = j >> 4, c = j & 15;
        float ve = t[2 * c][n], vo = t[2 * c + 1][n];
        uint32_t hi, lo;
        cvt_pair(ve, vo, hi, lo);
        g_BTh[bto + (size_t)(n0 + n) * Kh + (k0 >> 1) + c] = hi;
        g_BTl[bto + (size_t)(n0 + n) * Kh + (k0 >> 1) + c] = lo;
    }
}

// ---------------- fused front 2: hist + fold-U ----------------------------------
__global__ __launch_bounds__(256) void k_front2(const int* __restrict__ dst,
                                                const float* __restrict__ eenc_w,
                                                const float* __restrict__ eenc_b) {
    const int b = blockIdx.x;
    const int tid = threadIdx.x;
    if (b < 3125) {
        int i = b * 256 + tid;
        if (i < EE) atomicAdd(&g_cursor[dst[i]], 1);
    } else {
        int idx = (b - 3125) * 256 + tid;
        if (idx < LNUM * EIN_F * HH) {
            int h = idx & 3;
            int k = (idx >> 2) & 63;
            int l = idx >> 8;
            const float* wp = eenc_w + k * HID;
            float s = 0.f;
#pragma unroll 8
            for (int hid = 0; hid < HID; hid++) s += wp[hid] * g_V[(l * HID + hid) * HH + h];
            g_U[idx] = s;
        } else if (idx < LNUM * EIN_F * HH + LNUM * HH) {
            int j = idx - LNUM * EIN_F * HH;
            int l = j >> 2, h = j & 3;
            float s = 0.f;
            for (int hid = 0; hid < HID; hid++) s += eenc_b[hid] * g_V[(l * HID + hid) * HH + h];
            g_eebias[j] = s;
        }
    }
}

// ---------------- scan (also initializes cursor) --------------------------------
__global__ void k_scan() {
    __shared__ int sh[1024];
    const int t = threadIdx.x;
    const int chunk = (NN + 1023) / 1024;
    const int start = t * chunk;
    const int end = min(start + chunk, NN);
    int s = 0;
    for (int i = start; i < end; i++) s += g_cursor[i];
    sh[t] = s;
    __syncthreads();
    for (int o = 1; o < 1024; o <<= 1) {
        int v = (t >= o) ? sh[t - o] : 0;
        __syncthreads();
        sh[t] += v;
        __syncthreads();
    }
    int run = sh[t] - s;
    for (int i = start; i < end; i++) {
        int d = g_cursor[i];
        g_off[i] = run;
        g_cursor[i] = run;
        run += d;
    }
    if (t == 1023) g_off[NN] = sh[1023];
}

// ---------------- fused: scatter + ee GEMM --------------------------------------
__global__ __launch_bounds__(256) void k_scatter_ee(const int* __restrict__ src,
                                                    const int* __restrict__ dst,
                                                    const float* __restrict__ efeat) {
    __shared__ float fs[128 * 65];
    __shared__ float us[64 * 12];
    const int b = blockIdx.x;
    const int tid = threadIdx.x;
    if (b < 3125) {
        int i = b * 256 + tid;
        if (i < EE) {
            int p = atomicAdd(&g_cursor[dst[i]], 1);
            g_csr_src[p] = src[i];
            g_csr_eid[p] = i;
        }
    } else {
        const int e0 = (b - 3125) * 128;
        for (int i = tid; i < 128 * 64; i += 256) {
            int e = i >> 6, k = i & 63;
            fs[e * 65 + k] = efeat[(size_t)(e0 + e) * 64 + k];
        }
        for (int i = tid; i < LNUM * EIN_F * HH; i += 256) {
            int h = i & 3, k = (i >> 2) & 63, l = i >> 8;
            us[k * 12 + l * 4 + h] = g_U[i];
        }
        __syncthreads();
#pragma unroll
        for (int p0 = 0; p0 < 6; p0++) {
            int p = p0 * 256 + tid;
            int e = p & 127, out = p >> 7;
            const float* fp = &fs[e * 65];
            float acc = 0.f;
#pragma unroll
            for (int k = 0; k < 64; k++) acc += fp[k] * us[k * 12 + out];
            g_ee[(size_t)(e0 + e) * 12 + out] = acc + g_eebias[out];
        }
    }
}

// ---------------- bf16 3-split mma.sync GEMM, 128x64 tile, 2 CTAs/SM ------------
#define SST 20
#define BUFU 7680
__global__ __launch_bounds__(256, 2) void k_gemm_bf16(
    const float* __restrict__ A, const uint32_t* __restrict__ BTh,
    const uint32_t* __restrict__ BTl, const float* __restrict__ bias,
    float* __restrict__ C, int M, int K,
    const float* __restrict__ alp, const float* __restrict__ arp) {
    extern __shared__ uint32_t smu[];

    const int tid = threadIdx.x;
    const int wid = tid >> 5;
    const int lane = tid & 31;
    const int g = lane >> 2;
    const int tg = lane & 3;
    const int m0 = blockIdx.x * 128;
    const int col0 = blockIdx.y * 64;
    const int wm = wid >> 1;
    const int wn = wid & 1;
    const int Kh = K >> 1;
    const int nchunk = K >> 5;

    if (alp) {
        const int h = blockIdx.y;
        if (tid < 128) {
            int r = m0 + tid;
            if (r < M) g_el[r * 4 + h] = 0.f;
        } else {
            int r = m0 + tid - 128;
            if (r < M) g_er[r * 4 + h] = 0.f;
        }
    }

    const int fAr = tid >> 3, fAc = (tid & 7) << 2;
    const int fBr = tid >> 2, fBq = (tid & 3) << 2;

    const uint32_t smem_base = smem_u32(smu);
    const int l15 = lane & 15;
    const uint32_t aRowOff = (uint32_t)(((wm * 32 + l15) * SST + ((lane >> 4) & 1) * 4) * 4);
    const int bm = lane >> 3, br = lane & 7;
    const uint32_t bX4Off = (uint32_t)(((wn * 32 + (bm >> 1) * 8 + br) * SST + (bm & 1) * 4) * 4);

    float acc[2][4][4];
#pragma unroll
    for (int i = 0; i < 2; i++)
#pragma unroll
        for (int j = 0; j < 4; j++)
#pragma unroll
            for (int q = 0; q < 4; q++) acc[i][j][q] = 0.f;

    float4 stA[4];
    uint4 stBh, stBl;

#define LOADG(cc) do {                                                        \
    const int kc0 = (cc) << 5;                                                \
    _Pragma("unroll")                                                         \
    for (int t = 0; t < 4; t++) {                                             \
        int gr = min(m0 + fAr + t * 32, M - 1);                               \
        stA[t] = *(const float4*)(A + (size_t)gr * K + kc0 + fAc);            \
    }                                                                         \
    {                                                                         \
        size_t o = (size_t)(col0 + fBr) * Kh + ((cc) << 4) + fBq;             \
        stBh = *(const uint4*)(BTh + o);                                      \
        stBl = *(const uint4*)(BTl + o);                                      \
    }                                                                         \
} while (0)

#define STOREB(buf) do {                                                      \
    uint32_t* bA = smu + (buf)*BUFU;                                          \
    _Pragma("unroll")                                                         \
    for (int t = 0; t < 4; t++) {                                             \
        float4 v = stA[t];                                                    \
        uint32_t h01, l01, h23, l23;                                          \
        cvt_pair(v.x, v.y, h01, l01);                                         \
        cvt_pair(v.z, v.w, h23, l23);                                         \
        int so = (fAr + t * 32) * SST + (fAc >> 1);                           \
        *(uint2*)(bA + so) = make_uint2(h01, h23);                            \
        *(uint2*)(bA + 2560 + so) = make_uint2(l01, l23);                     \
    }                                                                         \
    {                                                                         \
        int so = fBr * SST + fBq;                                             \
        *(uint4*)(bA + 5120 + so) = stBh;                                     \
        *(uint4*)(bA + 6400 + so) = stBl;                                     \
    }                                                                         \
} while (0)

    LOADG(0);
    STOREB(0);
    __syncthreads();

    for (int c = 0; c < nchunk; c++) {
        const int cur = c & 1;
        const bool more = (c + 1 < nchunk);
        if (more) LOADG(c + 1);

        const uint32_t bufB = smem_base + (uint32_t)(cur * BUFU * 4);
#pragma unroll
        for (int ks = 0; ks < 2; ks++) {
            uint32_t ah[2][4], al_[2][4], bh[4][2], bl[4][2];
            const uint32_t aH = bufB + aRowOff + ks * 32;
            const uint32_t bH = bufB + 5120 * 4 + bX4Off + ks * 32;
#pragma unroll
            for (int ma = 0; ma < 2; ma++) {
                ldsm_x4(ah[ma], aH + ma * (16 * SST * 4));
                ldsm_x4(al_[ma], aH + 2560 * 4 + ma * (16 * SST * 4));
            }
#pragma unroll
            for (int p = 0; p < 2; p++) {
                uint32_t bt[4];
                ldsm_x4(bt, bH + p * (16 * SST * 4));
                bh[2 * p][0] = bt[0]; bh[2 * p][1] = bt[1];
                bh[2 * p + 1][0] = bt[2]; bh[2 * p + 1][1] = bt[3];
                ldsm_x4(bt, bH + 1280 * 4 + p * (16 * SST * 4));
                bl[2 * p][0] = bt[0]; bl[2 * p][1] = bt[1];
                bl[2 * p + 1][0] = bt[2]; bl[2 * p + 1][1] = bt[3];
            }
#pragma unroll
            for (int ma = 0; ma < 2; ma++)
#pragma unroll
                for (int na = 0; na < 4; na++) mma_bf16(acc[ma][na], ah[ma], bh[na]);
#pragma unroll
            for (int ma = 0; ma < 2; ma++)
#pragma unroll
                for (int na = 0; na < 4; na++) mma_bf16(acc[ma][na], ah[ma], bl[na]);
#pragma unroll
            for (int ma = 0; ma < 2; ma++)
#pragma unroll
                for (int na = 0; na < 4; na++) mma_bf16(acc[ma][na], al_[ma], bh[na]);
        }
        if (more) {
            STOREB(1 - cur);
            __syncthreads();
        }
    }

    // store C (+bias)
#pragma unroll
    for (int ma = 0; ma < 2; ma++) {
        const int r0 = m0 + wm * 32 + ma * 16 + g;
        const int r1 = r0 + 8;
#pragma unroll
        for (int na = 0; na < 4; na++) {
            const int cc = col0 + wn * 32 + na * 8 + 2 * tg;
            float b0 = 0.f, b1 = 0.f;
            if (bias) { b0 = __ldg(bias + cc); b1 = __ldg(bias + cc + 1); }
            if (r0 < M) {
                float2 o = make_float2(acc[ma][na][0] + b0, acc[ma][na][1] + b1);
                *(float2*)(C + (size_t)r0 * 256 + cc) = o;
            }
            if (r1 < M) {
                float2 o = make_float2(acc[ma][na][2] + b0, acc[ma][na][3] + b1);
                *(float2*)(C + (size_t)r1 * 256 + cc) = o;
            }
        }
    }

    // fused el/er: CTA's 64 cols = one head
    if (alp) {
        const int h = blockIdx.y;
        float av0[4], av1[4], rv0[4], rv1[4];
#pragma unroll
        for (int na = 0; na < 4; na++) {
            const int d = wn * 32 + na * 8 + 2 * tg;
            av0[na] = __ldg(alp + h * DD + d);
            av1[na] = __ldg(alp + h * DD + d + 1);
            rv0[na] = __ldg(arp + h * DD + d);
            rv1[na] = __ldg(arp + h * DD + d + 1);
        }
#pragma unroll
        for (int ma = 0; ma < 2; ma++) {
            float pel0 = 0.f, pel1 = 0.f, per0 = 0.f, per1 = 0.f;
#pragma unroll
            for (int na = 0; na < 4; na++) {
                pel0 += acc[ma][na][0] * av0[na] + acc[ma][na][1] * av1[na];
                pel1 += acc[ma][na][2] * av0[na] + acc[ma][na][3] * av1[na];
                per0 += acc[ma][na][0] * rv0[na] + acc[ma][na][1] * rv1[na];
                per1 += acc[ma][na][2] * rv0[na] + acc[ma][na][3] * rv1[na];
            }
#pragma unroll
            for (int o = 1; o < 4; o <<= 1) {
                pel0 += __shfl_xor_sync(0xffffffffu, pel0, o);
                pel1 += __shfl_xor_sync(0xffffffffu, pel1, o);
                per0 += __shfl_xor_sync(0xffffffffu, per0, o);
                per1 += __shfl_xor_sync(0xffffffffu, per1, o);
            }
            if (tg == 0) {
                const int r0 = m0 + wm * 32 + ma * 16 + g;
                const int r1 = r0 + 8;
                if (r0 < M) {
                    atomicAdd(&g_el[r0 * 4 + h], pel0);
                    atomicAdd(&g_er[r0 * 4 + h], per0);
                }
                if (r1 < M) {
                    atomicAdd(&g_el[r1 * 4 + h], pel1);
                    atomicAdd(&g_er[r1 * 4 + h], per1);
                }
            }
        }
    }
#undef LOADG
#undef STOREB
}

// ---------------- per-dst-node: softmax + aggregate + LN (two-pass, unroll 8) ---
__device__ __forceinline__ float lrelu(float e) { return e > 0.f ? e : 0.2f * e; }

__global__ __launch_bounds__(256) void k_edge(int l,
                                              const float* __restrict__ ln_g,
                                              const float* __restrict__ ln_b) {
    const int lane = threadIdx.x & 31;
    const int n = blockIdx.x * 8 + (threadIdx.x >> 5);
    if (n >= NN) return;
    const int beg = g_off[n], end = g_off[n + 1];
    const float4 er4 = *(const float4*)&g_er[n * 4];

    float s0 = 0.f, s1 = 0.f, s2 = 0.f, s3 = 0.f;
    for (int i = beg + lane; i < end; i += 32) {
        const int s = g_csr_src[i];
        const int eid = g_csr_eid[i];
        const float4 el4 = *(const float4*)&g_el[s * 4];
        const float4 ee4 = *(const float4*)&g_ee[(size_t)eid * 12 + l * 4];
        float4 e;
        e.x = __expf(lrelu(el4.x + er4.x + ee4.x)); s0 += e.x;
        e.y = __expf(lrelu(el4.y + er4.y + ee4.y)); s1 += e.y;
        e.z = __expf(lrelu(el4.z + er4.z + ee4.z)); s2 += e.z;
        e.w = __expf(lrelu(el4.w + er4.w + ee4.w)); s3 += e.w;
        *(float4*)&g_alpha[(size_t)i * 4] = e;
    }
#pragma unroll
    for (int o = 16; o; o >>= 1) {
        s0 += __shfl_xor_sync(0xffffffffu, s0, o);
        s1 += __shfl_xor_sync(0xffffffffu, s1, o);
        s2 += __shfl_xor_sync(0xffffffffu, s2, o);
        s3 += __shfl_xor_sync(0xffffffffu, s3, o);
    }
    __syncwarp();
    const int myhead = lane >> 3;
    const float rs_my = (myhead == 0) ? 1.f / s0 : (myhead == 1) ? 1.f / s1
                      : (myhead == 2) ? 1.f / s2 : 1.f / s3;

    float a0 = 0.f, a1 = 0.f, a2 = 0.f, a3 = 0.f, a4 = 0.f, a5 = 0.f, a6 = 0.f, a7 = 0.f;
    int i = beg;
    for (; i + 8 <= end; i += 8) {
        float aw[8];
        const float4* fr[8];
#pragma unroll
        for (int u = 0; u < 8; u++) {
            const int sx = g_csr_src[i + u];
            const float4 alv = *(const float4*)&g_alpha[(size_t)(i + u) * 4];
            aw[u] = ((myhead == 0) ? alv.x : (myhead == 1) ? alv.y
                    : (myhead == 2) ? alv.z : alv.w) * rs_my;
            fr[u] = (const float4*)(g_FEAT + (size_t)sx * HID + lane * 8);
        }
        float4 f0[8], f1[8];
#pragma unroll
        for (int u = 0; u < 8; u++) { f0[u] = __ldg(fr[u]); f1[u] = __ldg(fr[u] + 1); }
#pragma unroll
        for (int u = 0; u < 8; u++) {
            const float a = aw[u];
            a0 += a * f0[u].x; a1 += a * f0[u].y; a2 += a * f0[u].z; a3 += a * f0[u].w;
            a4 += a * f1[u].x; a5 += a * f1[u].y; a6 += a * f1[u].z; a7 += a * f1[u].w;
        }
    }
    for (; i < end; i++) {
        const int sA = g_csr_src[i];
        const float4 alv = *(const float4*)&g_alpha[(size_t)i * 4];
        const float a = ((myhead == 0) ? alv.x : (myhead == 1) ? alv.y
                        : (myhead == 2) ? alv.z : alv.w) * rs_my;
        const float4* frA = (const float4*)(g_FEAT + (size_t)sA * HID + lane * 8);
        const float4 fA0 = __ldg(frA), fA1 = __ldg(frA + 1);
        a0 += a * fA0.x; a1 += a * fA0.y; a2 += a * fA0.z; a3 += a * fA0.w;
        a4 += a * fA1.x; a5 += a * fA1.y; a6 += a * fA1.z; a7 += a * fA1.w;
    }

    const float4 r0 = *(const float4*)(g_X + (size_t)n * HID + lane * 8);
    const float4 r1 = *(const float4*)(g_X + (size_t)n * HID + lane * 8 + 4);
    float y[8];
    y[0] = fmaxf(a0, 0.f) + r0.x; y[1] = fmaxf(a1, 0.f) + r0.y;
    y[2] = fmaxf(a2, 0.f) + r0.z; y[3] = fmaxf(a3, 0.f) + r0.w;
    y[4] = fmaxf(a4, 0.f) + r1.x; y[5] = fmaxf(a5, 0.f) + r1.y;
    y[6] = fmaxf(a6, 0.f) + r1.z; y[7] = fmaxf(a7, 0.f) + r1.w;
    float sum = 0.f;
#pragma unroll
    for (int j = 0; j < 8; j++) sum += y[j];
#pragma unroll
    for (int o = 16; o; o >>= 1) sum += __shfl_xor_sync(0xffffffffu, sum, o);
    const float mu = sum * (1.f / 256.f);
    float vs = 0.f;
#pragma unroll
    for (int j = 0; j < 8; j++) { float d = y[j] - mu; vs += d * d; }
#pragma unroll
    for (int o = 16; o; o >>= 1) vs += __shfl_xor_sync(0xffffffffu, vs, o);
    const float rstd = rsqrtf(vs * (1.f / 256.f) + 1e-5f);
    const float* gp = ln_g + lane * 8;
    const float* bp = ln_b + lane * 8;
    float4 o0, o1;
    o0.x = (y[0] - mu) * rstd * gp[0] + bp[0];
    o0.y = (y[1] - mu) * rstd * gp[1] + bp[1];
    o0.z = (y[2] - mu) * rstd * gp[2] + bp[2];
    o0.w = (y[3] - mu) * rstd * gp[3] + bp[3];
    o1.x = (y[4] - mu) * rstd * gp[4] + bp[4];
    o1.y = (y[5] - mu) * rstd * gp[5] + bp[5];
    o1.z = (y[6] - mu) * rstd * gp[6] + bp[6];
    o1.w = (y[7] - mu) * rstd * gp[7] + bp[7];
    *(float4*)(g_X + (size_t)n * HID + lane * 8) = o0;
    *(float4*)(g_X + (size_t)n * HID + lane * 8 + 4) = o1;
}

// ---------------- launch ----------------
extern "C" void kernel_launch(void* const* d_in, const int* in_sizes, int n_in,
                              void* d_out, int out_size) {
    const float* h      = (const float*)d_in[0];
    const float* efeat  = (const float*)d_in[1];
    const int*   src    = (const int*)d_in[2];
    const int*   dst    = (const int*)d_in[3];
    const float* enc_w  = (const float*)d_in[4];
    const float* enc_b  = (const float*)d_in[5];
    const float* eenc_w = (const float*)d_in[6];
    const float* eenc_b = (const float*)d_in[7];
    const float* Wn     = (const float*)d_in[8];
    const float* We     = (const float*)d_in[9];
    const float* al     = (const float*)d_in[10];
    const float* ar     = (const float*)d_in[11];
    const float* ae     = (const float*)d_in[12];
    const float* ln_g   = (const float*)d_in[13];
    const float* ln_b   = (const float*)d_in[14];
    const float* out_w  = (const float*)d_in[15];
    const float* out_b  = (const float*)d_in[16];
    float* out = (float*)d_out;

    float *X, *FEAT;
    uint32_t *BTh, *BTl;
    cudaGetSymbolAddress((void**)&X, g_X);
    cudaGetSymbolAddress((void**)&FEAT, g_FEAT);
    cudaGetSymbolAddress((void**)&BTh, g_BTh);
    cudaGetSymbolAddress((void**)&BTl, g_BTl);

    const int DSM = 2 * BUFU * 4;
    cudaFuncSetAttribute(k_gemm_bf16, cudaFuncAttributeMaxDynamicSharedMemorySize, DSM);
    const int MTILES = divup(NN, 128);
    const dim3 ggrid(MTILES, 4);

    k_front1<<<496, 256>>>(We, ae, enc_w, Wn, out_w);                    // 0
    k_front2<<<3129, 256>>>(dst, eenc_w, eenc_b);                        // 1
    k_scan<<<1, 1024>>>();                                               // 2
    k_gemm_bf16<<<ggrid, 256, DSM>>>(h, BTh + BT_ENC, BTl + BT_ENC, enc_b,
                                     X, NN, IN_F, nullptr, nullptr);     // 3 <- ncu
    k_scatter_ee<<<3125 + EE / 128, 256>>>(src, dst, efeat);             // 4

    for (int l = 0; l < LNUM; l++) {
        k_gemm_bf16<<<ggrid, 256, DSM>>>(X, BTh + BT_WN(l), BTl + BT_WN(l), nullptr,
                                         FEAT, NN, HID,
                                         al + l * HH * DD, ar + l * HH * DD);
        k_edge<<<divup(NN, 8), 256>>>(l, ln_g + l * HID, ln_b + l * HID);
    }

    k_gemm_bf16<<<ggrid, 256, DSM>>>(X, BTh + BT_OUT, BTl + BT_OUT, out_b,
                                     out, NN, HID, nullptr, nullptr);
}

// round 15
// speedup vs baseline: 1.1880x; 1.1364x over previous
#include <cuda_runtime.h>
#include <cuda_bf16.h>
#include <cuda_fp16.h>
#include <cstdint>

#define NN   50000
#define EE   800000
#define IN_F 128
#define EIN_F 64
#define HID  256
#define OUTF 256
#define LNUM 3
#define HH   4
#define DD   64

// ---------------- device scratch (no cudaMalloc allowed) ----------------
__device__ __align__(16) float g_X[NN * HID];
__device__ __align__(16) uint32_t g_FEATH[NN * HID / 2];   // feat as half2
__device__ __align__(16) float g_el[NN * HH];
__device__ __align__(16) float g_er[NN * HH];
__device__ __align__(16) float g_ee[(size_t)EE * LNUM * HH];
__device__ __align__(16) float g_alpha[(size_t)EE * HH];
__device__ int g_off[NN + 1];
__device__ int g_cursor[NN];
__device__ int g_csr_src[EE];
__device__ int g_csr_eid[EE];
__device__ float g_V[LNUM * HID * HH];
__device__ float g_U[LNUM * EIN_F * HH];
__device__ float g_eebias[LNUM * HH];
#define BT_ENC 0
#define BT_WN(l) (16384 + (l) * 32768)
#define BT_OUT (16384 + 3 * 32768)
__device__ __align__(16) uint32_t g_BTh[16384 + 4 * 32768];
__device__ __align__(16) uint32_t g_BTl[16384 + 4 * 32768];

static inline int divup(int a, int b) { return (a + b - 1) / b; }

// ---------------- bf16 helpers ----------------
__device__ __forceinline__ uint32_t pack2(__nv_bfloat16 a, __nv_bfloat16 b) {
    __nv_bfloat162 t;
    t.x = a; t.y = b;
    return *reinterpret_cast<uint32_t*>(&t);
}
__device__ __forceinline__ void cvt_pair(float a, float b, uint32_t& hi, uint32_t& lo) {
    __nv_bfloat16 ha = __float2bfloat16(a), hb = __float2bfloat16(b);
    hi = pack2(ha, hb);
    float ra = a - __bfloat162float(ha);
    float rb = b - __bfloat162float(hb);
    lo = pack2(__float2bfloat16(ra), __float2bfloat16(rb));
}
__device__ __forceinline__ void mma_bf16(float* c, const uint32_t* a, const uint32_t* b) {
    asm volatile(
        "mma.sync.aligned.m16n8k16.row.col.f32.bf16.bf16.f32 "
        "{%0,%1,%2,%3}, {%4,%5,%6,%7}, {%8,%9}, {%0,%1,%2,%3};"
        : "+f"(c[0]), "+f"(c[1]), "+f"(c[2]), "+f"(c[3])
        : "r"(a[0]), "r"(a[1]), "r"(a[2]), "r"(a[3]), "r"(b[0]), "r"(b[1]));
}
__device__ __forceinline__ uint32_t smem_u32(const void* p) {
    uint32_t a;
    asm("{ .reg .u64 t; cvta.to.shared.u64 t, %1; cvt.u32.u64 %0, t; }" : "=r"(a) : "l"(p));
    return a;
}
__device__ __forceinline__ void ldsm_x4(uint32_t* r, uint32_t a) {
    asm volatile("ldmatrix.sync.aligned.m8n8.x4.shared.b16 {%0,%1,%2,%3}, [%4];"
                 : "=r"(r[0]), "=r"(r[1]), "=r"(r[2]), "=r"(r[3]) : "r"(a));
}

// ---------------- fused front 1: zero-cursor + fold-V + ALL weight transposes ---
__global__ __launch_bounds__(256) void k_front1(const float* __restrict__ We,
                                                const float* __restrict__ ae,
                                                const float* __restrict__ enc_w,
                                                const float* __restrict__ Wn,
                                                const float* __restrict__ out_w) {
    __shared__ float t[32][33];
    const int b = blockIdx.x;
    const int tid = threadIdx.x;
    if (b < 196) {
        int i = b * 256 + tid;
        if (i < NN) g_cursor[i] = 0;
        return;
    }
    if (b < 208) {
        int idx = (b - 196) * 256 + tid;
        if (idx < LNUM * HID * HH) {
            int h = idx & 3;
            int hid = (idx >> 2) & (HID - 1);
            int l = idx >> 10;
            const float* wp = We + ((size_t)(l * HID + hid)) * HID + h * DD;
            const float* ap = ae + (l * HH + h) * DD;
            float s = 0.f;
#pragma unroll 8
            for (int d = 0; d < DD; d++) s += wp[d] * ap[d];
            g_V[idx] = s;
        }
        return;
    }
    const float* src;
    int n0, k0, K, bto;
    if (b < 240) {
        const int b2 = b - 208;
        src = enc_w; K = IN_F; bto = BT_ENC;
        n0 = (b2 & 7) * 32;
        k0 = (b2 >> 3) * 32;
    } else {
        const int b3 = b - 240;
        const int w = b3 >> 6;
        src = (w < 3) ? (Wn + (size_t)w * HID * HID) : out_w;
        K = HID; bto = 16384 + w * 32768;
        const int b4 = b3 & 63;
        n0 = (b4 & 7) * 32;
        k0 = (b4 >> 3) * 32;
    }
    const int tx = tid & 31, ty = tid >> 5;
#pragma unroll
    for (int i = 0; i < 32; i += 8)
        t[ty + i][tx] = src[(size_t)(k0 + ty + i) * HID + n0 + tx];
    __syncthreads();
    const int Kh = K >> 1;
#pragma unroll
    for (int it = 0; it < 2; it++) {
        int j = tid + it * 256;
        int n = j >> 4, c = j & 15;
        float ve = t[2 * c][n], vo = t[2 * c + 1][n];
        uint32_t hi, lo;
        cvt_pair(ve, vo, hi, lo);
        g_BTh[bto + (size_t)(n0 + n) * Kh + (k0 >> 1) + c] = hi;
        g_BTl[bto + (size_t)(n0 + n) * Kh + (k0 >> 1) + c] = lo;
    }
}

// ---------------- fused front 2: hist + fold-U ----------------------------------
__global__ __launch_bounds__(256) void k_front2(const int* __restrict__ dst,
                                                const float* __restrict__ eenc_w,
                                                const float* __restrict__ eenc_b) {
    const int b = blockIdx.x;
    const int tid = threadIdx.x;
    if (b < 3125) {
        int i = b * 256 + tid;
        if (i < EE) atomicAdd(&g_cursor[dst[i]], 1);
    } else {
        int idx = (b - 3125) * 256 + tid;
        if (idx < LNUM * EIN_F * HH) {
            int h = idx & 3;
            int k = (idx >> 2) & 63;
            int l = idx >> 8;
            const float* wp = eenc_w + k * HID;
            float s = 0.f;
#pragma unroll 8
            for (int hid = 0; hid < HID; hid++) s += wp[hid] * g_V[(l * HID + hid) * HH + h];
            g_U[idx] = s;
        } else if (idx < LNUM * EIN_F * HH + LNUM * HH) {
            int j = idx - LNUM * EIN_F * HH;
            int l = j >> 2, h = j & 3;
            float s = 0.f;
            for (int hid = 0; hid < HID; hid++) s += eenc_b[hid] * g_V[(l * HID + hid) * HH + h];
            g_eebias[j] = s;
        }
    }
}

// ---------------- scan (also initializes cursor) --------------------------------
__global__ void k_scan() {
    __shared__ int sh[1024];
    const int t = threadIdx.x;
    const int chunk = (NN + 1023) / 1024;
    const int start = t * chunk;
    const int end = min(start + chunk, NN);
    int s = 0;
    for (int i = start; i < end; i++) s += g_cursor[i];
    sh[t] = s;
    __syncthreads();
    for (int o = 1; o < 1024; o <<= 1) {
        int v = (t >= o) ? sh[t - o] : 0;
        __syncthreads();
        sh[t] += v;
        __syncthreads();
    }
    int run = sh[t] - s;
    for (int i = start; i < end; i++) {
        int d = g_cursor[i];
        g_off[i] = run;
        g_cursor[i] = run;
        run += d;
    }
    if (t == 1023) g_off[NN] = sh[1023];
}

// ---------------- fused: scatter + ee GEMM --------------------------------------
__global__ __launch_bounds__(256) void k_scatter_ee(const int* __restrict__ src,
                                                    const int* __restrict__ dst,
                                                    const float* __restrict__ efeat) {
    __shared__ float fs[128 * 65];
    __shared__ float us[64 * 12];
    const int b = blockIdx.x;
    const int tid = threadIdx.x;
    if (b < 3125) {
        int i = b * 256 + tid;
        if (i < EE) {
            int p = atomicAdd(&g_cursor[dst[i]], 1);
            g_csr_src[p] = src[i];
            g_csr_eid[p] = i;
        }
    } else {
        const int e0 = (b - 3125) * 128;
        for (int i = tid; i < 128 * 64; i += 256) {
            int e = i >> 6, k = i & 63;
            fs[e * 65 + k] = efeat[(size_t)(e0 + e) * 64 + k];
        }
        for (int i = tid; i < LNUM * EIN_F * HH; i += 256) {
            int h = i & 3, k = (i >> 2) & 63, l = i >> 8;
            us[k * 12 + l * 4 + h] = g_U[i];
        }
        __syncthreads();
#pragma unroll
        for (int p0 = 0; p0 < 6; p0++) {
            int p = p0 * 256 + tid;
            int e = p & 127, out = p >> 7;
            const float* fp = &fs[e * 65];
            float acc = 0.f;
#pragma unroll
            for (int k = 0; k < 64; k++) acc += fp[k] * us[k * 12 + out];
            g_ee[(size_t)(e0 + e) * 12 + out] = acc + g_eebias[out];
        }
    }
}

// ---------------- bf16 3-split mma.sync GEMM, 128x64 tile, 2 CTAs/SM ------------
// alp != null (feat GEMM): write FEAT as half2 + accumulate el/er.
// alp == null: write fp32 C (+bias).
#define SST 20
#define BUFU 7680
__global__ __launch_bounds__(256, 2) void k_gemm_bf16(
    const float* __restrict__ A, const uint32_t* __restrict__ BTh,
    const uint32_t* __restrict__ BTl, const float* __restrict__ bias,
    float* __restrict__ C, int M, int K,
    const float* __restrict__ alp, const float* __restrict__ arp) {
    extern __shared__ uint32_t smu[];

    const int tid = threadIdx.x;
    const int wid = tid >> 5;
    const int lane = tid & 31;
    const int g = lane >> 2;
    const int tg = lane & 3;
    const int m0 = blockIdx.x * 128;
    const int col0 = blockIdx.y * 64;
    const int wm = wid >> 1;
    const int wn = wid & 1;
    const int Kh = K >> 1;
    const int nchunk = K >> 5;

    if (alp) {
        const int h = blockIdx.y;
        if (tid < 128) {
            int r = m0 + tid;
            if (r < M) g_el[r * 4 + h] = 0.f;
        } else {
            int r = m0 + tid - 128;
            if (r < M) g_er[r * 4 + h] = 0.f;
        }
    }

    const int fAr = tid >> 3, fAc = (tid & 7) << 2;
    const int fBr = tid >> 2, fBq = (tid & 3) << 2;

    const uint32_t smem_base = smem_u32(smu);
    const int l15 = lane & 15;
    const uint32_t aRowOff = (uint32_t)(((wm * 32 + l15) * SST + ((lane >> 4) & 1) * 4) * 4);
    const int bm = lane >> 3, br = lane & 7;
    const uint32_t bX4Off = (uint32_t)(((wn * 32 + (bm >> 1) * 8 + br) * SST + (bm & 1) * 4) * 4);

    float acc[2][4][4];
#pragma unroll
    for (int i = 0; i < 2; i++)
#pragma unroll
        for (int j = 0; j < 4; j++)
#pragma unroll
            for (int q = 0; q < 4; q++) acc[i][j][q] = 0.f;

    float4 stA[4];
    uint4 stBh, stBl;

#define LOADG(cc) do {                                                        \
    const int kc0 = (cc) << 5;                                                \
    _Pragma("unroll")                                                         \
    for (int t = 0; t < 4; t++) {                                             \
        int gr = min(m0 + fAr + t * 32, M - 1);                               \
        stA[t] = *(const float4*)(A + (size_t)gr * K + kc0 + fAc);            \
    }                                                                         \
    {                                                                         \
        size_t o = (size_t)(col0 + fBr) * Kh + ((cc) << 4) + fBq;             \
        stBh = *(const uint4*)(BTh + o);                                      \
        stBl = *(const uint4*)(BTl + o);                                      \
    }                                                                         \
} while (0)

#define STOREB(buf) do {                                                      \
    uint32_t* bA = smu + (buf)*BUFU;                                          \
    _Pragma("unroll")                                                         \
    for (int t = 0; t < 4; t++) {                                             \
        float4 v = stA[t];                                                    \
        uint32_t h01, l01, h23, l23;                                          \
        cvt_pair(v.x, v.y, h01, l01);                                         \
        cvt_pair(v.z, v.w, h23, l23);                                         \
        int so = (fAr + t * 32) * SST + (fAc >> 1);                           \
        *(uint2*)(bA + so) = make_uint2(h01, h23);                            \
        *(uint2*)(bA + 2560 + so) = make_uint2(l01, l23);                     \
    }                                                                         \
    {                                                                         \
        int so = fBr * SST + fBq;                                             \
        *(uint4*)(bA + 5120 + so) = stBh;                                     \
        *(uint4*)(bA + 6400 + so) = stBl;                                     \
    }                                                                         \
} while (0)

    LOADG(0);
    STOREB(0);
    __syncthreads();

    for (int c = 0; c < nchunk; c++) {
        const int cur = c & 1;
        const bool more = (c + 1 < nchunk);
        if (more) LOADG(c + 1);

        const uint32_t bufB = smem_base + (uint32_t)(cur * BUFU * 4);
#pragma unroll
        for (int ks = 0; ks < 2; ks++) {
            uint32_t ah[2][4], al_[2][4], bh[4][2], bl[4][2];
            const uint32_t aH = bufB + aRowOff + ks * 32;
            const uint32_t bH = bufB + 5120 * 4 + bX4Off + ks * 32;
#pragma unroll
            for (int ma = 0; ma < 2; ma++) {
                ldsm_x4(ah[ma], aH + ma * (16 * SST * 4));
                ldsm_x4(al_[ma], aH + 2560 * 4 + ma * (16 * SST * 4));
            }
#pragma unroll
            for (int p = 0; p < 2; p++) {
                uint32_t bt[4];
                ldsm_x4(bt, bH + p * (16 * SST * 4));
                bh[2 * p][0] = bt[0]; bh[2 * p][1] = bt[1];
                bh[2 * p + 1][0] = bt[2]; bh[2 * p + 1][1] = bt[3];
                ldsm_x4(bt, bH + 1280 * 4 + p * (16 * SST * 4));
                bl[2 * p][0] = bt[0]; bl[2 * p][1] = bt[1];
                bl[2 * p + 1][0] = bt[2]; bl[2 * p + 1][1] = bt[3];
            }
#pragma unroll
            for (int ma = 0; ma < 2; ma++)
#pragma unroll
                for (int na = 0; na < 4; na++) mma_bf16(acc[ma][na], ah[ma], bh[na]);
#pragma unroll
            for (int ma = 0; ma < 2; ma++)
#pragma unroll
                for (int na = 0; na < 4; na++) mma_bf16(acc[ma][na], ah[ma], bl[na]);
#pragma unroll
            for (int ma = 0; ma < 2; ma++)
#pragma unroll
                for (int na = 0; na < 4; na++) mma_bf16(acc[ma][na], al_[ma], bh[na]);
        }
        if (more) {
            STOREB(1 - cur);
            __syncthreads();
        }
    }

    if (alp) {
        // feat GEMM: write half2 FEAT
#pragma unroll
        for (int ma = 0; ma < 2; ma++) {
            const int r0 = m0 + wm * 32 + ma * 16 + g;
            const int r1 = r0 + 8;
#pragma unroll
            for (int na = 0; na < 4; na++) {
                const int cc = col0 + wn * 32 + na * 8 + 2 * tg;
                if (r0 < M) {
                    __half2 hv = __floats2half2_rn(acc[ma][na][0], acc[ma][na][1]);
                    g_FEATH[(size_t)r0 * 128 + (cc >> 1)] = *reinterpret_cast<uint32_t*>(&hv);
                }
                if (r1 < M) {
                    __half2 hv = __floats2half2_rn(acc[ma][na][2], acc[ma][na][3]);
                    g_FEATH[(size_t)r1 * 128 + (cc >> 1)] = *reinterpret_cast<uint32_t*>(&hv);
                }
            }
        }
        // fused el/er
        const int h = blockIdx.y;
        float av0[4], av1[4], rv0[4], rv1[4];
#pragma unroll
        for (int na = 0; na < 4; na++) {
            const int d = wn * 32 + na * 8 + 2 * tg;
            av0[na] = __ldg(alp + h * DD + d);
            av1[na] = __ldg(alp + h * DD + d + 1);
            rv0[na] = __ldg(arp + h * DD + d);
            rv1[na] = __ldg(arp + h * DD + d + 1);
        }
#pragma unroll
        for (int ma = 0; ma < 2; ma++) {
            float pel0 = 0.f, pel1 = 0.f, per0 = 0.f, per1 = 0.f;
#pragma unroll
            for (int na = 0; na < 4; na++) {
                pel0 += acc[ma][na][0] * av0[na] + acc[ma][na][1] * av1[na];
                pel1 += acc[ma][na][2] * av0[na] + acc[ma][na][3] * av1[na];
                per0 += acc[ma][na][0] * rv0[na] + acc[ma][na][1] * rv1[na];
                per1 += acc[ma][na][2] * rv0[na] + acc[ma][na][3] * rv1[na];
            }
#pragma unroll
            for (int o = 1; o < 4; o <<= 1) {
                pel0 += __shfl_xor_sync(0xffffffffu, pel0, o);
                pel1 += __shfl_xor_sync(0xffffffffu, pel1, o);
                per0 += __shfl_xor_sync(0xffffffffu, per0, o);
                per1 += __shfl_xor_sync(0xffffffffu, per1, o);
            }
            if (tg == 0) {
                const int r0 = m0 + wm * 32 + ma * 16 + g;
                const int r1 = r0 + 8;
                if (r0 < M) {
                    atomicAdd(&g_el[r0 * 4 + h], pel0);
                    atomicAdd(&g_er[r0 * 4 + h], per0);
                }
                if (r1 < M) {
                    atomicAdd(&g_el[r1 * 4 + h], pel1);
                    atomicAdd(&g_er[r1 * 4 + h], per1);
                }
            }
        }
    } else {
        // plain GEMM: fp32 C (+bias)
#pragma unroll
        for (int ma = 0; ma < 2; ma++) {
            const int r0 = m0 + wm * 32 + ma * 16 + g;
            const int r1 = r0 + 8;
#pragma unroll
            for (int na = 0; na < 4; na++) {
                const int cc = col0 + wn * 32 + na * 8 + 2 * tg;
                float b0 = 0.f, b1 = 0.f;
                if (bias) { b0 = __ldg(bias + cc); b1 = __ldg(bias + cc + 1); }
                if (r0 < M) {
                    float2 o = make_float2(acc[ma][na][0] + b0, acc[ma][na][1] + b1);
                    *(float2*)(C + (size_t)r0 * 256 + cc) = o;
                }
                if (r1 < M) {
                    float2 o = make_float2(acc[ma][na][2] + b0, acc[ma][na][3] + b1);
                    *(float2*)(C + (size_t)r1 * 256 + cc) = o;
                }
            }
        }
    }
#undef LOADG
#undef STOREB
}

// ---------------- per-dst-node: softmax + aggregate (half2 feat) + LN -----------
__device__ __forceinline__ float lrelu(float e) { return e > 0.f ? e : 0.2f * e; }

__global__ __launch_bounds__(256) void k_edge(int l,
                                              const float* __restrict__ ln_g,
                                              const float* __restrict__ ln_b) {
    const int lane = threadIdx.x & 31;
    const int n = blockIdx.x * 8 + (threadIdx.x >> 5);
    if (n >= NN) return;
    const int beg = g_off[n], end = g_off[n + 1];
    const float4 er4 = *(const float4*)&g_er[n * 4];

    float s0 = 0.f, s1 = 0.f, s2 = 0.f, s3 = 0.f;
    for (int i = beg + lane; i < end; i += 32) {
        const int s = g_csr_src[i];
        const int eid = g_csr_eid[i];
        const float4 el4 = *(const float4*)&g_el[s * 4];
        const float4 ee4 = *(const float4*)&g_ee[(size_t)eid * 12 + l * 4];
        float4 e;
        e.x = __expf(lrelu(el4.x + er4.x + ee4.x)); s0 += e.x;
        e.y = __expf(lrelu(el4.y + er4.y + ee4.y)); s1 += e.y;
        e.z = __expf(lrelu(el4.z + er4.z + ee4.z)); s2 += e.z;
        e.w = __expf(lrelu(el4.w + er4.w + ee4.w)); s3 += e.w;
        *(float4*)&g_alpha[(size_t)i * 4] = e;
    }
#pragma unroll
    for (int o = 16; o; o >>= 1) {
        s0 += __shfl_xor_sync(0xffffffffu, s0, o);
        s1 += __shfl_xor_sync(0xffffffffu, s1, o);
        s2 += __shfl_xor_sync(0xffffffffu, s2, o);
        s3 += __shfl_xor_sync(0xffffffffu, s3, o);
    }
    __syncwarp();
    const int myhead = lane >> 3;
    const float rs_my = (myhead == 0) ? 1.f / s0 : (myhead == 1) ? 1.f / s1
                      : (myhead == 2) ? 1.f / s2 : 1.f / s3;

    float a0 = 0.f, a1 = 0.f, a2 = 0.f, a3 = 0.f, a4 = 0.f, a5 = 0.f, a6 = 0.f, a7 = 0.f;
    int i = beg;
    for (; i + 4 <= end; i += 4) {
        float aw[4];
        const uint4* fr[4];
#pragma unroll
        for (int u = 0; u < 4; u++) {
            const int sx = g_csr_src[i + u];
            const float4 alv = *(const float4*)&g_alpha[(size_t)(i + u) * 4];
            aw[u] = ((myhead == 0) ? alv.x : (myhead == 1) ? alv.y
                    : (myhead == 2) ? alv.z : alv.w) * rs_my;
            fr[u] = (const uint4*)(g_FEATH + (size_t)sx * 128 + lane * 4);
        }
        uint4 fv[4];
#pragma unroll
        for (int u = 0; u < 4; u++) fv[u] = __ldg(fr[u]);
#pragma unroll
        for (int u = 0; u < 4; u++) {
            const float a = aw[u];
            float2 p0 = __half22float2(*reinterpret_cast<__half2*>(&fv[u].x));
            float2 p1 = __half22float2(*reinterpret_cast<__half2*>(&fv[u].y));
            float2 p2 = __half22float2(*reinterpret_cast<__half2*>(&fv[u].z));
            float2 p3 = __half22float2(*reinterpret_cast<__half2*>(&fv[u].w));
            a0 += a * p0.x; a1 += a * p0.y; a2 += a * p1.x; a3 += a * p1.y;
            a4 += a * p2.x; a5 += a * p2.y; a6 += a * p3.x; a7 += a * p3.y;
        }
    }
    for (; i < end; i++) {
        const int sA = g_csr_src[i];
        const float4 alv = *(const float4*)&g_alpha[(size_t)i * 4];
        const float a = ((myhead == 0) ? alv.x : (myhead == 1) ? alv.y
                        : (myhead == 2) ? alv.z : alv.w) * rs_my;
        uint4 fv = __ldg((const uint4*)(g_FEATH + (size_t)sA * 128 + lane * 4));
        float2 p0 = __half22float2(*reinterpret_cast<__half2*>(&fv.x));
        float2 p1 = __half22float2(*reinterpret_cast<__half2*>(&fv.y));
        float2 p2 = __half22float2(*reinterpret_cast<__half2*>(&fv.z));
        float2 p3 = __half22float2(*reinterpret_cast<__half2*>(&fv.w));
        a0 += a * p0.x; a1 += a * p0.y; a2 += a * p1.x; a3 += a * p1.y;
        a4 += a * p2.x; a5 += a * p2.y; a6 += a * p3.x; a7 += a * p3.y;
    }

    const float4 r0 = *(const float4*)(g_X + (size_t)n * HID + lane * 8);
    const float4 r1 = *(const float4*)(g_X + (size_t)n * HID + lane * 8 + 4);
    float y[8];
    y[0] = fmaxf(a0, 0.f) + r0.x; y[1] = fmaxf(a1, 0.f) + r0.y;
    y[2] = fmaxf(a2, 0.f) + r0.z; y[3] = fmaxf(a3, 0.f) + r0.w;
    y[4] = fmaxf(a4, 0.f) + r1.x; y[5] = fmaxf(a5, 0.f) + r1.y;
    y[6] = fmaxf(a6, 0.f) + r1.z; y[7] = fmaxf(a7, 0.f) + r1.w;
    float sum = 0.f;
#pragma unroll
    for (int j = 0; j < 8; j++) sum += y[j];
#pragma unroll
    for (int o = 16; o; o >>= 1) sum += __shfl_xor_sync(0xffffffffu, sum, o);
    const float mu = sum * (1.f / 256.f);
    float vs = 0.f;
#pragma unroll
    for (int j = 0; j < 8; j++) { float d = y[j] - mu; vs += d * d; }
#pragma unroll
    for (int o = 16; o; o >>= 1) vs += __shfl_xor_sync(0xffffffffu, vs, o);
    const float rstd = rsqrtf(vs * (1.f / 256.f) + 1e-5f);
    const float* gp = ln_g + lane * 8;
    const float* bp = ln_b + lane * 8;
    float4 o0, o1;
    o0.x = (y[0] - mu) * rstd * gp[0] + bp[0];
    o0.y = (y[1] - mu) * rstd * gp[1] + bp[1];
    o0.z = (y[2] - mu) * rstd * gp[2] + bp[2];
    o0.w = (y[3] - mu) * rstd * gp[3] + bp[3];
    o1.x = (y[4] - mu) * rstd * gp[4] + bp[4];
    o1.y = (y[5] - mu) * rstd * gp[5] + bp[5];
    o1.z = (y[6] - mu) * rstd * gp[6] + bp[6];
    o1.w = (y[7] - mu) * rstd * gp[7] + bp[7];
    *(float4*)(g_X + (size_t)n * HID + lane * 8) = o0;
    *(float4*)(g_X + (size_t)n * HID + lane * 8 + 4) = o1;
}

// ---------------- launch ----------------
extern "C" void kernel_launch(void* const* d_in, const int* in_sizes, int n_in,
                              void* d_out, int out_size) {
    const float* h      = (const float*)d_in[0];
    const float* efeat  = (const float*)d_in[1];
    const int*   src    = (const int*)d_in[2];
    const int*   dst    = (const int*)d_in[3];
    const float* enc_w  = (const float*)d_in[4];
    const float* enc_b  = (const float*)d_in[5];
    const float* eenc_w = (const float*)d_in[6];
    const float* eenc_b = (const float*)d_in[7];
    const float* Wn     = (const float*)d_in[8];
    const float* We     = (const float*)d_in[9];
    const float* al     = (const float*)d_in[10];
    const float* ar     = (const float*)d_in[11];
    const float* ae     = (const float*)d_in[12];
    const float* ln_g   = (const float*)d_in[13];
    const float* ln_b   = (const float*)d_in[14];
    const float* out_w  = (const float*)d_in[15];
    const float* out_b  = (const float*)d_in[16];
    float* out = (float*)d_out;

    float* X;
    uint32_t *BTh, *BTl;
    cudaGetSymbolAddress((void**)&X, g_X);
    cudaGetSymbolAddress((void**)&BTh, g_BTh);
    cudaGetSymbolAddress((void**)&BTl, g_BTl);

    const int DSM = 2 * BUFU * 4;
    cudaFuncSetAttribute(k_gemm_bf16, cudaFuncAttributeMaxDynamicSharedMemorySize, DSM);
    const int MTILES = divup(NN, 128);
    const dim3 ggrid(MTILES, 4);

    k_front1<<<496, 256>>>(We, ae, enc_w, Wn, out_w);                    // 0
    k_front2<<<3129, 256>>>(dst, eenc_w, eenc_b);                        // 1
    k_scan<<<1, 1024>>>();                                               // 2
    k_gemm_bf16<<<ggrid, 256, DSM>>>(h, BTh + BT_ENC, BTl + BT_ENC, enc_b,
                                     X, NN, IN_F, nullptr, nullptr);     // 3 <- ncu
    k_scatter_ee<<<3125 + EE / 128, 256>>>(src, dst, efeat);             // 4

    for (int l = 0; l < LNUM; l++) {
        k_gemm_bf16<<<ggrid, 256, DSM>>>(X, BTh + BT_WN(l), BTl + BT_WN(l), nullptr,
                                         nullptr, NN, HID,
                                         al + l * HH * DD, ar + l * HH * DD);
        k_edge<<<divup(NN, 8), 256>>>(l, ln_g + l * HID, ln_b + l * HID);
    }

    k_gemm_bf16<<<ggrid, 256, DSM>>>(X, BTh + BT_OUT, BTl + BT_OUT, out_b,
                                     out, NN, HID, nullptr, nullptr);
}

// round 16
// speedup vs baseline: 1.2918x; 1.0874x over previous
#include <cuda_runtime.h>
#include <cuda_bf16.h>
#include <cuda_fp16.h>
#include <cstdint>

#define NN   50000
#define EE   800000
#define IN_F 128
#define EIN_F 64
#define HID  256
#define OUTF 256
#define LNUM 3
#define HH   4
#define DD   64

// ---------------- device scratch (no cudaMalloc allowed) ----------------
__device__ __align__(16) float g_X[NN * HID];
__device__ __align__(16) uint32_t g_FEATH[NN * HID / 2];   // feat as half2
__device__ __align__(16) float g_el[NN * HH];
__device__ __align__(16) float g_er[NN * HH];
__device__ __align__(16) float g_ee[(size_t)EE * LNUM * HH];
__device__ __align__(16) float g_alpha[(size_t)EE * HH];
__device__ int g_off[NN + 1];
__device__ int g_cursor[NN];
__device__ int g_csr_src[EE];
__device__ int g_csr_eid[EE];
__device__ float g_V[LNUM * HID * HH];
__device__ float g_U[LNUM * EIN_F * HH];
__device__ float g_eebias[LNUM * HH];
#define BT_ENC 0
#define BT_WN(l) (16384 + (l) * 32768)
#define BT_OUT (16384 + 3 * 32768)
__device__ __align__(16) uint32_t g_BTh[16384 + 4 * 32768];
__device__ __align__(16) uint32_t g_BTl[16384 + 4 * 32768];
// fp16 transposed weights (half2-packed along K): 4 x 256x128 u32 (Wn x3 + out)
__device__ __align__(16) uint32_t g_WF16[4 * 32768];

static inline int divup(int a, int b) { return (a + b - 1) / b; }

// ---------------- helpers ----------------
__device__ __forceinline__ uint32_t pack2(__nv_bfloat16 a, __nv_bfloat16 b) {
    __nv_bfloat162 t;
    t.x = a; t.y = b;
    return *reinterpret_cast<uint32_t*>(&t);
}
__device__ __forceinline__ void cvt_pair(float a, float b, uint32_t& hi, uint32_t& lo) {
    __nv_bfloat16 ha = __float2bfloat16(a), hb = __float2bfloat16(b);
    hi = pack2(ha, hb);
    float ra = a - __bfloat162float(ha);
    float rb = b - __bfloat162float(hb);
    lo = pack2(__float2bfloat16(ra), __float2bfloat16(rb));
}
__device__ __forceinline__ uint32_t packh2(float a, float b) {
    __half2 t = __floats2half2_rn(a, b);
    return *reinterpret_cast<uint32_t*>(&t);
}
__device__ __forceinline__ void mma_bf16(float* c, const uint32_t* a, const uint32_t* b) {
    asm volatile(
        "mma.sync.aligned.m16n8k16.row.col.f32.bf16.bf16.f32 "
        "{%0,%1,%2,%3}, {%4,%5,%6,%7}, {%8,%9}, {%0,%1,%2,%3};"
        : "+f"(c[0]), "+f"(c[1]), "+f"(c[2]), "+f"(c[3])
        : "r"(a[0]), "r"(a[1]), "r"(a[2]), "r"(a[3]), "r"(b[0]), "r"(b[1]));
}
__device__ __forceinline__ void mma_f16(float* c, const uint32_t* a, const uint32_t* b) {
    asm volatile(
        "mma.sync.aligned.m16n8k16.row.col.f32.f16.f16.f32 "
        "{%0,%1,%2,%3}, {%4,%5,%6,%7}, {%8,%9}, {%0,%1,%2,%3};"
        : "+f"(c[0]), "+f"(c[1]), "+f"(c[2]), "+f"(c[3])
        : "r"(a[0]), "r"(a[1]), "r"(a[2]), "r"(a[3]), "r"(b[0]), "r"(b[1]));
}
__device__ __forceinline__ uint32_t smem_u32(const void* p) {
    uint32_t a;
    asm("{ .reg .u64 t; cvta.to.shared.u64 t, %1; cvt.u32.u64 %0, t; }" : "=r"(a) : "l"(p));
    return a;
}
__device__ __forceinline__ void ldsm_x4(uint32_t* r, uint32_t a) {
    asm volatile("ldmatrix.sync.aligned.m8n8.x4.shared.b16 {%0,%1,%2,%3}, [%4];"
                 : "=r"(r[0]), "=r"(r[1]), "=r"(r[2]), "=r"(r[3]) : "r"(a));
}

// ---------------- fused front 1: zero-cursor + fold-V + ALL weight transposes ---
__global__ __launch_bounds__(256) void k_front1(const float* __restrict__ We,
                                                const float* __restrict__ ae,
                                                const float* __restrict__ enc_w,
                                                const float* __restrict__ Wn,
                                                const float* __restrict__ out_w) {
    __shared__ float t[32][33];
    const int b = blockIdx.x;
    const int tid = threadIdx.x;
    if (b < 196) {
        int i = b * 256 + tid;
        if (i < NN) g_cursor[i] = 0;
        return;
    }
    if (b < 208) {
        int idx = (b - 196) * 256 + tid;
        if (idx < LNUM * HID * HH) {
            int h = idx & 3;
            int hid = (idx >> 2) & (HID - 1);
            int l = idx >> 10;
            const float* wp = We + ((size_t)(l * HID + hid)) * HID + h * DD;
            const float* ap = ae + (l * HH + h) * DD;
            float s = 0.f;
#pragma unroll 8
            for (int d = 0; d < DD; d++) s += wp[d] * ap[d];
            g_V[idx] = s;
        }
        return;
    }
    const float* src;
    int n0, k0, K, bto, w = -1;
    if (b < 240) {
        const int b2 = b - 208;
        src = enc_w; K = IN_F; bto = BT_ENC;
        n0 = (b2 & 7) * 32;
        k0 = (b2 >> 3) * 32;
    } else {
        const int b3 = b - 240;
        w = b3 >> 6;
        src = (w < 3) ? (Wn + (size_t)w * HID * HID) : out_w;
        K = HID; bto = 16384 + w * 32768;
        const int b4 = b3 & 63;
        n0 = (b4 & 7) * 32;
        k0 = (b4 >> 3) * 32;
    }
    const int tx = tid & 31, ty = tid >> 5;
#pragma unroll
    for (int i = 0; i < 32; i += 8)
        t[ty + i][tx] = src[(size_t)(k0 + ty + i) * HID + n0 + tx];
    __syncthreads();
    const int Kh = K >> 1;
#pragma unroll
    for (int it = 0; it < 2; it++) {
        int j = tid + it * 256;
        int n = j >> 4, c = j & 15;
        float ve = t[2 * c][n], vo = t[2 * c + 1][n];
        uint32_t hi, lo;
        cvt_pair(ve, vo, hi, lo);
        size_t o = (size_t)(n0 + n) * Kh + (k0 >> 1) + c;
        g_BTh[bto + o] = hi;
        g_BTl[bto + o] = lo;
        if (w >= 0) g_WF16[w * 32768 + o] = packh2(ve, vo);
    }
}

// ---------------- fused front 2: hist + fold-U ----------------------------------
__global__ __launch_bounds__(256) void k_front2(const int* __restrict__ dst,
                                                const float* __restrict__ eenc_w,
                                                const float* __restrict__ eenc_b) {
    const int b = blockIdx.x;
    const int tid = threadIdx.x;
    if (b < 3125) {
        int i = b * 256 + tid;
        if (i < EE) atomicAdd(&g_cursor[dst[i]], 1);
    } else {
        int idx = (b - 3125) * 256 + tid;
        if (idx < LNUM * EIN_F * HH) {
            int h = idx & 3;
            int k = (idx >> 2) & 63;
            int l = idx >> 8;
            const float* wp = eenc_w + k * HID;
            float s = 0.f;
#pragma unroll 8
            for (int hid = 0; hid < HID; hid++) s += wp[hid] * g_V[(l * HID + hid) * HH + h];
            g_U[idx] = s;
        } else if (idx < LNUM * EIN_F * HH + LNUM * HH) {
            int j = idx - LNUM * EIN_F * HH;
            int l = j >> 2, h = j & 3;
            float s = 0.f;
            for (int hid = 0; hid < HID; hid++) s += eenc_b[hid] * g_V[(l * HID + hid) * HH + h];
            g_eebias[j] = s;
        }
    }
}

// ---------------- scan (also initializes cursor) --------------------------------
__global__ void k_scan() {
    __shared__ int sh[1024];
    const int t = threadIdx.x;
    const int chunk = (NN + 1023) / 1024;
    const int start = t * chunk;
    const int end = min(start + chunk, NN);
    int s = 0;
    for (int i = start; i < end; i++) s += g_cursor[i];
    sh[t] = s;
    __syncthreads();
    for (int o = 1; o < 1024; o <<= 1) {
        int v = (t >= o) ? sh[t - o] : 0;
        __syncthreads();
        sh[t] += v;
        __syncthreads();
    }
    int run = sh[t] - s;
    for (int i = start; i < end; i++) {
        int d = g_cursor[i];
        g_off[i] = run;
        g_cursor[i] = run;
        run += d;
    }
    if (t == 1023) g_off[NN] = sh[1023];
}

// ---------------- fused: scatter + ee GEMM --------------------------------------
__global__ __launch_bounds__(256) void k_scatter_ee(const int* __restrict__ src,
                                                    const int* __restrict__ dst,
                                                    const float* __restrict__ efeat) {
    __shared__ float fs[128 * 65];
    __shared__ float us[64 * 12];
    const int b = blockIdx.x;
    const int tid = threadIdx.x;
    if (b < 3125) {
        int i = b * 256 + tid;
        if (i < EE) {
            int p = atomicAdd(&g_cursor[dst[i]], 1);
            g_csr_src[p] = src[i];
            g_csr_eid[p] = i;
        }
    } else {
        const int e0 = (b - 3125) * 128;
        for (int i = tid; i < 128 * 64; i += 256) {
            int e = i >> 6, k = i & 63;
            fs[e * 65 + k] = efeat[(size_t)(e0 + e) * 64 + k];
        }
        for (int i = tid; i < LNUM * EIN_F * HH; i += 256) {
            int h = i & 3, k = (i >> 2) & 63, l = i >> 8;
            us[k * 12 + l * 4 + h] = g_U[i];
        }
        __syncthreads();
#pragma unroll
        for (int p0 = 0; p0 < 6; p0++) {
            int p = p0 * 256 + tid;
            int e = p & 127, out = p >> 7;
            const float* fp = &fs[e * 65];
            float acc = 0.f;
#pragma unroll
            for (int k = 0; k < 64; k++) acc += fp[k] * us[k * 12 + out];
            g_ee[(size_t)(e0 + e) * 12 + out] = acc + g_eebias[out];
        }
    }
}

// ---------------- bf16 3-split GEMM (enc & out): fp32 C (+bias) -----------------
#define SST 20
#define BUFU 7680
__global__ __launch_bounds__(256, 2) void k_gemm_bf16(
    const float* __restrict__ A, const uint32_t* __restrict__ BTh,
    const uint32_t* __restrict__ BTl, const float* __restrict__ bias,
    float* __restrict__ C, int M, int K) {
    extern __shared__ uint32_t smu[];

    const int tid = threadIdx.x;
    const int wid = tid >> 5;
    const int lane = tid & 31;
    const int g = lane >> 2;
    const int tg = lane & 3;
    const int m0 = blockIdx.x * 128;
    const int col0 = blockIdx.y * 64;
    const int wm = wid >> 1;
    const int wn = wid & 1;
    const int Kh = K >> 1;
    const int nchunk = K >> 5;

    const int fAr = tid >> 3, fAc = (tid & 7) << 2;
    const int fBr = tid >> 2, fBq = (tid & 3) << 2;

    const uint32_t smem_base = smem_u32(smu);
    const int l15 = lane & 15;
    const uint32_t aRowOff = (uint32_t)(((wm * 32 + l15) * SST + ((lane >> 4) & 1) * 4) * 4);
    const int bm = lane >> 3, br = lane & 7;
    const uint32_t bX4Off = (uint32_t)(((wn * 32 + (bm >> 1) * 8 + br) * SST + (bm & 1) * 4) * 4);

    float acc[2][4][4];
#pragma unroll
    for (int i = 0; i < 2; i++)
#pragma unroll
        for (int j = 0; j < 4; j++)
#pragma unroll
            for (int q = 0; q < 4; q++) acc[i][j][q] = 0.f;

    float4 stA[4];
    uint4 stBh, stBl;

#define LOADG(cc) do {                                                        \
    const int kc0 = (cc) << 5;                                                \
    _Pragma("unroll")                                                         \
    for (int t = 0; t < 4; t++) {                                             \
        int gr = min(m0 + fAr + t * 32, M - 1);                               \
        stA[t] = *(const float4*)(A + (size_t)gr * K + kc0 + fAc);            \
    }                                                                         \
    {                                                                         \
        size_t o = (size_t)(col0 + fBr) * Kh + ((cc) << 4) + fBq;             \
        stBh = *(const uint4*)(BTh + o);                                      \
        stBl = *(const uint4*)(BTl + o);                                      \
    }                                                                         \
} while (0)

#define STOREB(buf) do {                                                      \
    uint32_t* bA = smu + (buf)*BUFU;                                          \
    _Pragma("unroll")                                                         \
    for (int t = 0; t < 4; t++) {                                             \
        float4 v = stA[t];                                                    \
        uint32_t h01, l01, h23, l23;                                          \
        cvt_pair(v.x, v.y, h01, l01);                                         \
        cvt_pair(v.z, v.w, h23, l23);                                         \
        int so = (fAr + t * 32) * SST + (fAc >> 1);                           \
        *(uint2*)(bA + so) = make_uint2(h01, h23);                            \
        *(uint2*)(bA + 2560 + so) = make_uint2(l01, l23);                     \
    }                                                                         \
    {                                                                         \
        int so = fBr * SST + fBq;                                             \
        *(uint4*)(bA + 5120 + so) = stBh;                                     \
        *(uint4*)(bA + 6400 + so) = stBl;                                     \
    }                                                                         \
} while (0)

    LOADG(0);
    STOREB(0);
    __syncthreads();

    for (int c = 0; c < nchunk; c++) {
        const int cur = c & 1;
        const bool more = (c + 1 < nchunk);
        if (more) LOADG(c + 1);

        const uint32_t bufB = smem_base + (uint32_t)(cur * BUFU * 4);
#pragma unroll
        for (int ks = 0; ks < 2; ks++) {
            uint32_t ah[2][4], al_[2][4], bh[4][2], bl[4][2];
            const uint32_t aH = bufB + aRowOff + ks * 32;
            const uint32_t bH = bufB + 5120 * 4 + bX4Off + ks * 32;
#pragma unroll
            for (int ma = 0; ma < 2; ma++) {
                ldsm_x4(ah[ma], aH + ma * (16 * SST * 4));
                ldsm_x4(al_[ma], aH + 2560 * 4 + ma * (16 * SST * 4));
            }
#pragma unroll
            for (int p = 0; p < 2; p++) {
                uint32_t bt[4];
                ldsm_x4(bt, bH + p * (16 * SST * 4));
                bh[2 * p][0] = bt[0]; bh[2 * p][1] = bt[1];
                bh[2 * p + 1][0] = bt[2]; bh[2 * p + 1][1] = bt[3];
                ldsm_x4(bt, bH + 1280 * 4 + p * (16 * SST * 4));
                bl[2 * p][0] = bt[0]; bl[2 * p][1] = bt[1];
                bl[2 * p + 1][0] = bt[2]; bl[2 * p + 1][1] = bt[3];
            }
#pragma unroll
            for (int ma = 0; ma < 2; ma++)
#pragma unroll
                for (int na = 0; na < 4; na++) mma_bf16(acc[ma][na], ah[ma], bh[na]);
#pragma unroll
            for (int ma = 0; ma < 2; ma++)
#pragma unroll
                for (int na = 0; na < 4; na++) mma_bf16(acc[ma][na], ah[ma], bl[na]);
#pragma unroll
            for (int ma = 0; ma < 2; ma++)
#pragma unroll
                for (int na = 0; na < 4; na++) mma_bf16(acc[ma][na], al_[ma], bh[na]);
        }
        if (more) {
            STOREB(1 - cur);
            __syncthreads();
        }
    }

#pragma unroll
    for (int ma = 0; ma < 2; ma++) {
        const int r0 = m0 + wm * 32 + ma * 16 + g;
        const int r1 = r0 + 8;
#pragma unroll
        for (int na = 0; na < 4; na++) {
            const int cc = col0 + wn * 32 + na * 8 + 2 * tg;
            float b0 = 0.f, b1 = 0.f;
            if (bias) { b0 = __ldg(bias + cc); b1 = __ldg(bias + cc + 1); }
            if (r0 < M) {
                float2 o = make_float2(acc[ma][na][0] + b0, acc[ma][na][1] + b1);
                *(float2*)(C + (size_t)r0 * 256 + cc) = o;
            }
            if (r1 < M) {
                float2 o = make_float2(acc[ma][na][2] + b0, acc[ma][na][3] + b1);
                *(float2*)(C + (size_t)r1 * 256 + cc) = o;
            }
        }
    }
#undef LOADG
#undef STOREB
}

// ---------------- fp16 single-term GEMM (feat): FEATH half2 + el/er -------------
#define BUF16 3840   // u32/buffer: A 128*20=2560, B 64*20=1280
__global__ __launch_bounds__(256, 2) void k_gemm_f16(
    const float* __restrict__ A, const uint32_t* __restrict__ WF,
    int M, const float* __restrict__ alp, const float* __restrict__ arp) {
    extern __shared__ uint32_t smu[];
    const int K = HID;

    const int tid = threadIdx.x;
    const int wid = tid >> 5;
    const int lane = tid & 31;
    const int g = lane >> 2;
    const int tg = lane & 3;
    const int m0 = blockIdx.x * 128;
    const int col0 = blockIdx.y * 64;
    const int wm = wid >> 1;
    const int wn = wid & 1;
    const int Kh = K >> 1;
    const int nchunk = K >> 5;

    {
        const int h = blockIdx.y;
        if (tid < 128) {
            int r = m0 + tid;
            if (r < M) g_el[r * 4 + h] = 0.f;
        } else {
            int r = m0 + tid - 128;
            if (r < M) g_er[r * 4 + h] = 0.f;
        }
    }

    const int fAr = tid >> 3, fAc = (tid & 7) << 2;
    const int fBr = tid >> 2, fBq = (tid & 3) << 2;

    const uint32_t smem_base = smem_u32(smu);
    const int l15 = lane & 15;
    const uint32_t aRowOff = (uint32_t)(((wm * 32 + l15) * SST + ((lane >> 4) & 1) * 4) * 4);
    const int bm = lane >> 3, br = lane & 7;
    const uint32_t bX4Off = (uint32_t)(((wn * 32 + (bm >> 1) * 8 + br) * SST + (bm & 1) * 4) * 4);

    float acc[2][4][4];
#pragma unroll
    for (int i = 0; i < 2; i++)
#pragma unroll
        for (int j = 0; j < 4; j++)
#pragma unroll
            for (int q = 0; q < 4; q++) acc[i][j][q] = 0.f;

    float4 stA[4];
    uint4 stB;

#define LOADG16(cc) do {                                                      \
    const int kc0 = (cc) << 5;                                                \
    _Pragma("unroll")                                                         \
    for (int t = 0; t < 4; t++) {                                             \
        int gr = min(m0 + fAr + t * 32, M - 1);                               \
        stA[t] = *(const float4*)(A + (size_t)gr * K + kc0 + fAc);            \
    }                                                                         \
    stB = *(const uint4*)(WF + (size_t)(col0 + fBr) * Kh + ((cc) << 4) + fBq);\
} while (0)

#define STOREB16(buf) do {                                                    \
    uint32_t* bA = smu + (buf)*BUF16;                                         \
    _Pragma("unroll")                                                         \
    for (int t = 0; t < 4; t++) {                                             \
        float4 v = stA[t];                                                    \
        int so = (fAr + t * 32) * SST + (fAc >> 1);                           \
        *(uint2*)(bA + so) = make_uint2(packh2(v.x, v.y), packh2(v.z, v.w));  \
    }                                                                         \
    *(uint4*)(bA + 2560 + fBr * SST + fBq) = stB;                             \
} while (0)

    LOADG16(0);
    STOREB16(0);
    __syncthreads();

    for (int c = 0; c < nchunk; c++) {
        const int cur = c & 1;
        const bool more = (c + 1 < nchunk);
        if (more) LOADG16(c + 1);

        const uint32_t bufB = smem_base + (uint32_t)(cur * BUF16 * 4);
#pragma unroll
        for (int ks = 0; ks < 2; ks++) {
            uint32_t ah[2][4], bh[4][2];
            const uint32_t aH = bufB + aRowOff + ks * 32;
            const uint32_t bH = bufB + 2560 * 4 + bX4Off + ks * 32;
#pragma unroll
            for (int ma = 0; ma < 2; ma++)
                ldsm_x4(ah[ma], aH + ma * (16 * SST * 4));
#pragma unroll
            for (int p = 0; p < 2; p++) {
                uint32_t bt[4];
                ldsm_x4(bt, bH + p * (16 * SST * 4));
                bh[2 * p][0] = bt[0]; bh[2 * p][1] = bt[1];
                bh[2 * p + 1][0] = bt[2]; bh[2 * p + 1][1] = bt[3];
            }
#pragma unroll
            for (int ma = 0; ma < 2; ma++)
#pragma unroll
                for (int na = 0; na < 4; na++) mma_f16(acc[ma][na], ah[ma], bh[na]);
        }
        if (more) {
            STOREB16(1 - cur);
            __syncthreads();
        }
    }

    // FEATH half2 epilogue
#pragma unroll
    for (int ma = 0; ma < 2; ma++) {
        const int r0 = m0 + wm * 32 + ma * 16 + g;
        const int r1 = r0 + 8;
#pragma unroll
        for (int na = 0; na < 4; na++) {
            const int cc = col0 + wn * 32 + na * 8 + 2 * tg;
            if (r0 < M)
                g_FEATH[(size_t)r0 * 128 + (cc >> 1)] = packh2(acc[ma][na][0], acc[ma][na][1]);
            if (r1 < M)
                g_FEATH[(size_t)r1 * 128 + (cc >> 1)] = packh2(acc[ma][na][2], acc[ma][na][3]);
        }
    }
    // fused el/er
    {
        const int h = blockIdx.y;
        float av0[4], av1[4], rv0[4], rv1[4];
#pragma unroll
        for (int na = 0; na < 4; na++) {
            const int d = wn * 32 + na * 8 + 2 * tg;
            av0[na] = __ldg(alp + h * DD + d);
            av1[na] = __ldg(alp + h * DD + d + 1);
            rv0[na] = __ldg(arp + h * DD + d);
            rv1[na] = __ldg(arp + h * DD + d + 1);
        }
#pragma unroll
        for (int ma = 0; ma < 2; ma++) {
            float pel0 = 0.f, pel1 = 0.f, per0 = 0.f, per1 = 0.f;
#pragma unroll
            for (int na = 0; na < 4; na++) {
                pel0 += acc[ma][na][0] * av0[na] + acc[ma][na][1] * av1[na];
                pel1 += acc[ma][na][2] * av0[na] + acc[ma][na][3] * av1[na];
                per0 += acc[ma][na][0] * rv0[na] + acc[ma][na][1] * rv1[na];
                per1 += acc[ma][na][2] * rv0[na] + acc[ma][na][3] * rv1[na];
            }
#pragma unroll
            for (int o = 1; o < 4; o <<= 1) {
                pel0 += __shfl_xor_sync(0xffffffffu, pel0, o);
                pel1 += __shfl_xor_sync(0xffffffffu, pel1, o);
                per0 += __shfl_xor_sync(0xffffffffu, per0, o);
                per1 += __shfl_xor_sync(0xffffffffu, per1, o);
            }
            if (tg == 0) {
                const int r0 = m0 + wm * 32 + ma * 16 + g;
                const int r1 = r0 + 8;
                if (r0 < M) {
                    atomicAdd(&g_el[r0 * 4 + h], pel0);
                    atomicAdd(&g_er[r0 * 4 + h], per0);
                }
                if (r1 < M) {
                    atomicAdd(&g_el[r1 * 4 + h], pel1);
                    atomicAdd(&g_er[r1 * 4 + h], per1);
                }
            }
        }
    }
#undef LOADG16
#undef STOREB16
}

// ---------------- per-dst-node: softmax + aggregate (half2 feat) + LN -----------
__device__ __forceinline__ float lrelu(float e) { return e > 0.f ? e : 0.2f * e; }

__global__ __launch_bounds__(256) void k_edge(int l,
                                              const float* __restrict__ ln_g,
                                              const float* __restrict__ ln_b) {
    const int lane = threadIdx.x & 31;
    const int n = blockIdx.x * 8 + (threadIdx.x >> 5);
    if (n >= NN) return;
    const int beg = g_off[n], end = g_off[n + 1];
    const float4 er4 = *(const float4*)&g_er[n * 4];

    float s0 = 0.f, s1 = 0.f, s2 = 0.f, s3 = 0.f;
    for (int i = beg + lane; i < end; i += 32) {
        const int s = g_csr_src[i];
        const int eid = g_csr_eid[i];
        const float4 el4 = *(const float4*)&g_el[s * 4];
        const float4 ee4 = *(const float4*)&g_ee[(size_t)eid * 12 + l * 4];
        float4 e;
        e.x = __expf(lrelu(el4.x + er4.x + ee4.x)); s0 += e.x;
        e.y = __expf(lrelu(el4.y + er4.y + ee4.y)); s1 += e.y;
        e.z = __expf(lrelu(el4.z + er4.z + ee4.z)); s2 += e.z;
        e.w = __expf(lrelu(el4.w + er4.w + ee4.w)); s3 += e.w;
        *(float4*)&g_alpha[(size_t)i * 4] = e;
    }
#pragma unroll
    for (int o = 16; o; o >>= 1) {
        s0 += __shfl_xor_sync(0xffffffffu, s0, o);
        s1 += __shfl_xor_sync(0xffffffffu, s1, o);
        s2 += __shfl_xor_sync(0xffffffffu, s2, o);
        s3 += __shfl_xor_sync(0xffffffffu, s3, o);
    }
    __syncwarp();
    const int myhead = lane >> 3;
    const float rs_my = (myhead == 0) ? 1.f / s0 : (myhead == 1) ? 1.f / s1
                      : (myhead == 2) ? 1.f / s2 : 1.f / s3;

    float a0 = 0.f, a1 = 0.f, a2 = 0.f, a3 = 0.f, a4 = 0.f, a5 = 0.f, a6 = 0.f, a7 = 0.f;
    int i = beg;
    for (; i + 4 <= end; i += 4) {
        float aw[4];
        const uint4* fr[4];
#pragma unroll
        for (int u = 0; u < 4; u++) {
            const int sx = g_csr_src[i + u];
            const float4 alv = *(const float4*)&g_alpha[(size_t)(i + u) * 4];
            aw[u] = ((myhead == 0) ? alv.x : (myhead == 1) ? alv.y
                    : (myhead == 2) ? alv.z : alv.w) * rs_my;
            fr[u] = (const uint4*)(g_FEATH + (size_t)sx * 128 + lane * 4);
        }
        uint4 fv[4];
#pragma unroll
        for (int u = 0; u < 4; u++) fv[u] = __ldg(fr[u]);
#pragma unroll
        for (int u = 0; u < 4; u++) {
            const float a = aw[u];
            float2 p0 = __half22float2(*reinterpret_cast<__half2*>(&fv[u].x));
            float2 p1 = __half22float2(*reinterpret_cast<__half2*>(&fv[u].y));
            float2 p2 = __half22float2(*reinterpret_cast<__half2*>(&fv[u].z));
            float2 p3 = __half22float2(*reinterpret_cast<__half2*>(&fv[u].w));
            a0 += a * p0.x; a1 += a * p0.y; a2 += a * p1.x; a3 += a * p1.y;
            a4 += a * p2.x; a5 += a * p2.y; a6 += a * p3.x; a7 += a * p3.y;
        }
    }
    for (; i < end; i++) {
        const int sA = g_csr_src[i];
        const float4 alv = *(const float4*)&g_alpha[(size_t)i * 4];
        const float a = ((myhead == 0) ? alv.x : (myhead == 1) ? alv.y
                        : (myhead == 2) ? alv.z : alv.w) * rs_my;
        uint4 fv = __ldg((const uint4*)(g_FEATH + (size_t)sA * 128 + lane * 4));
        float2 p0 = __half22float2(*reinterpret_cast<__half2*>(&fv.x));
        float2 p1 = __half22float2(*reinterpret_cast<__half2*>(&fv.y));
        float2 p2 = __half22float2(*reinterpret_cast<__half2*>(&fv.z));
        float2 p3 = __half22float2(*reinterpret_cast<__half2*>(&fv.w));
        a0 += a * p0.x; a1 += a * p0.y; a2 += a * p1.x; a3 += a * p1.y;
        a4 += a * p2.x; a5 += a * p2.y; a6 += a * p3.x; a7 += a * p3.y;
    }

    const float4 r0 = *(const float4*)(g_X + (size_t)n * HID + lane * 8);
    const float4 r1 = *(const float4*)(g_X + (size_t)n * HID + lane * 8 + 4);
    float y[8];
    y[0] = fmaxf(a0, 0.f) + r0.x; y[1] = fmaxf(a1, 0.f) + r0.y;
    y[2] = fmaxf(a2, 0.f) + r0.z; y[3] = fmaxf(a3, 0.f) + r0.w;
    y[4] = fmaxf(a4, 0.f) + r1.x; y[5] = fmaxf(a5, 0.f) + r1.y;
    y[6] = fmaxf(a6, 0.f) + r1.z; y[7] = fmaxf(a7, 0.f) + r1.w;
    float sum = 0.f;
#pragma unroll
    for (int j = 0; j < 8; j++) sum += y[j];
#pragma unroll
    for (int o = 16; o; o >>= 1) sum += __shfl_xor_sync(0xffffffffu, sum, o);
    const float mu = sum * (1.f / 256.f);
    float vs = 0.f;
#pragma unroll
    for (int j = 0; j < 8; j++) { float d = y[j] - mu; vs += d * d; }
#pragma unroll
    for (int o = 16; o; o >>= 1) vs += __shfl_xor_sync(0xffffffffu, vs, o);
    const float rstd = rsqrtf(vs * (1.f / 256.f) + 1e-5f);
    const float* gp = ln_g + lane * 8;
    const float* bp = ln_b + lane * 8;
    float4 o0, o1;
    o0.x = (y[0] - mu) * rstd * gp[0] + bp[0];
    o0.y = (y[1] - mu) * rstd * gp[1] + bp[1];
    o0.z = (y[2] - mu) * rstd * gp[2] + bp[2];
    o0.w = (y[3] - mu) * rstd * gp[3] + bp[3];
    o1.x = (y[4] - mu) * rstd * gp[4] + bp[4];
    o1.y = (y[5] - mu) * rstd * gp[5] + bp[5];
    o1.z = (y[6] - mu) * rstd * gp[6] + bp[6];
    o1.w = (y[7] - mu) * rstd * gp[7] + bp[7];
    *(float4*)(g_X + (size_t)n * HID + lane * 8) = o0;
    *(float4*)(g_X + (size_t)n * HID + lane * 8 + 4) = o1;
}

// ---------------- launch ----------------
extern "C" void kernel_launch(void* const* d_in, const int* in_sizes, int n_in,
                              void* d_out, int out_size) {
    const float* h      = (const float*)d_in[0];
    const float* efeat  = (const float*)d_in[1];
    const int*   src    = (const int*)d_in[2];
    const int*   dst    = (const int*)d_in[3];
    const float* enc_w  = (const float*)d_in[4];
    const float* enc_b  = (const float*)d_in[5];
    const float* eenc_w = (const float*)d_in[6];
    const float* eenc_b = (const float*)d_in[7];
    const float* Wn     = (const float*)d_in[8];
    const float* We     = (const float*)d_in[9];
    const float* al     = (const float*)d_in[10];
    const float* ar     = (const float*)d_in[11];
    const float* ae     = (const float*)d_in[12];
    const float* ln_g   = (const float*)d_in[13];
    const float* ln_b   = (const float*)d_in[14];
    const float* out_w  = (const float*)d_in[15];
    const float* out_b  = (const float*)d_in[16];
    float* out = (float*)d_out;

    float* X;
    uint32_t *BTh, *BTl, *WF;
    cudaGetSymbolAddress((void**)&X, g_X);
    cudaGetSymbolAddress((void**)&BTh, g_BTh);
    cudaGetSymbolAddress((void**)&BTl, g_BTl);
    cudaGetSymbolAddress((void**)&WF, g_WF16);

    const int DSM = 2 * BUFU * 4;
    const int DSM16 = 2 * BUF16 * 4;
    cudaFuncSetAttribute(k_gemm_bf16, cudaFuncAttributeMaxDynamicSharedMemorySize, DSM);
    cudaFuncSetAttribute(k_gemm_f16, cudaFuncAttributeMaxDynamicSharedMemorySize, DSM16);
    const int MTILES = divup(NN, 128);
    const dim3 ggrid(MTILES, 4);

    k_front1<<<496, 256>>>(We, ae, enc_w, Wn, out_w);                    // 0
    k_front2<<<3129, 256>>>(dst, eenc_w, eenc_b);                        // 1
    k_scan<<<1, 1024>>>();                                               // 2
    k_gemm_bf16<<<ggrid, 256, DSM>>>(h, BTh + BT_ENC, BTl + BT_ENC, enc_b,
                                     X, NN, IN_F);                       // 3 <- ncu
    k_scatter_ee<<<3125 + EE / 128, 256>>>(src, dst, efeat);             // 4

    for (int l = 0; l < LNUM; l++) {
        k_gemm_f16<<<ggrid, 256, DSM16>>>(X, WF + l * 32768, NN,
                                          al + l * HH * DD, ar + l * HH * DD);
        k_edge<<<divup(NN, 8), 256>>>(l, ln_g + l * HID, ln_b + l * HID);
    }

    k_gemm_bf16<<<ggrid, 256, DSM>>>(X, BTh + BT_OUT, BTl + BT_OUT, out_b,
                                     out, NN, HID);
}

// round 17
// speedup vs baseline: 1.3243x; 1.0252x over previous
#include <cuda_runtime.h>
#include <cuda_bf16.h>
#include <cuda_fp16.h>
#include <cstdint>

#define NN   50000
#define EE   800000
#define IN_F 128
#define EIN_F 64
#define HID  256
#define OUTF 256
#define LNUM 3
#define HH   4
#define DD   64

// ---------------- device scratch (no cudaMalloc allowed) ----------------
__device__ __align__(16) float g_X[NN * HID];
__device__ __align__(16) uint32_t g_FEATH[NN * HID / 2];   // feat as half2
__device__ __align__(16) float g_el[NN * HH];
__device__ __align__(16) float g_er[NN * HH];
__device__ __align__(16) float g_ee[(size_t)EE * LNUM * HH];
__device__ __align__(16) float g_alpha[(size_t)EE * HH];
__device__ int g_off[NN + 1];
__device__ int g_cursor[NN];
__device__ int g_csr_src[EE];
__device__ int g_csr_eid[EE];
__device__ float g_V[LNUM * HID * HH];
__device__ float g_U[LNUM * EIN_F * HH];
__device__ float g_eebias[LNUM * HH];
#define BT_ENC 0
__device__ __align__(16) uint32_t g_BTh[16384];
__device__ __align__(16) uint32_t g_BTl[16384];
// fp16 transposed weights (half2-packed along K): Wn x3 + out, 256x128 u32 each
__device__ __align__(16) uint32_t g_WF16[4 * 32768];

static inline int divup(int a, int b) { return (a + b - 1) / b; }

// ---------------- helpers ----------------
__device__ __forceinline__ uint32_t pack2(__nv_bfloat16 a, __nv_bfloat16 b) {
    __nv_bfloat162 t;
    t.x = a; t.y = b;
    return *reinterpret_cast<uint32_t*>(&t);
}
__device__ __forceinline__ void cvt_pair(float a, float b, uint32_t& hi, uint32_t& lo) {
    __nv_bfloat16 ha = __float2bfloat16(a), hb = __float2bfloat16(b);
    hi = pack2(ha, hb);
    float ra = a - __bfloat162float(ha);
    float rb = b - __bfloat162float(hb);
    lo = pack2(__float2bfloat16(ra), __float2bfloat16(rb));
}
__device__ __forceinline__ uint32_t packh2(float a, float b) {
    __half2 t = __floats2half2_rn(a, b);
    return *reinterpret_cast<uint32_t*>(&t);
}
__device__ __forceinline__ void mma_bf16(float* c, const uint32_t* a, const uint32_t* b) {
    asm volatile(
        "mma.sync.aligned.m16n8k16.row.col.f32.bf16.bf16.f32 "
        "{%0,%1,%2,%3}, {%4,%5,%6,%7}, {%8,%9}, {%0,%1,%2,%3};"
        : "+f"(c[0]), "+f"(c[1]), "+f"(c[2]), "+f"(c[3])
        : "r"(a[0]), "r"(a[1]), "r"(a[2]), "r"(a[3]), "r"(b[0]), "r"(b[1]));
}
__device__ __forceinline__ void mma_f16(float* c, const uint32_t* a, const uint32_t* b) {
    asm volatile(
        "mma.sync.aligned.m16n8k16.row.col.f32.f16.f16.f32 "
        "{%0,%1,%2,%3}, {%4,%5,%6,%7}, {%8,%9}, {%0,%1,%2,%3};"
        : "+f"(c[0]), "+f"(c[1]), "+f"(c[2]), "+f"(c[3])
        : "r"(a[0]), "r"(a[1]), "r"(a[2]), "r"(a[3]), "r"(b[0]), "r"(b[1]));
}
__device__ __forceinline__ uint32_t smem_u32(const void* p) {
    uint32_t a;
    asm("{ .reg .u64 t; cvta.to.shared.u64 t, %1; cvt.u32.u64 %0, t; }" : "=r"(a) : "l"(p));
    return a;
}
__device__ __forceinline__ void ldsm_x4(uint32_t* r, uint32_t a) {
    asm volatile("ldmatrix.sync.aligned.m8n8.x4.shared.b16 {%0,%1,%2,%3}, [%4];"
                 : "=r"(r[0]), "=r"(r[1]), "=r"(r[2]), "=r"(r[3]) : "r"(a));
}

// ---------------- fused front 1: zero-cursor + fold-V + ALL weight transposes ---
__global__ __launch_bounds__(256) void k_front1(const float* __restrict__ We,
                                                const float* __restrict__ ae,
                                                const float* __restrict__ enc_w,
                                                const float* __restrict__ Wn,
                                                const float* __restrict__ out_w) {
    __shared__ float t[32][33];
    const int b = blockIdx.x;
    const int tid = threadIdx.x;
    if (b < 196) {
        int i = b * 256 + tid;
        if (i < NN) g_cursor[i] = 0;
        return;
    }
    if (b < 208) {
        int idx = (b - 196) * 256 + tid;
        if (idx < LNUM * HID * HH) {
            int h = idx & 3;
            int hid = (idx >> 2) & (HID - 1);
            int l = idx >> 10;
            const float* wp = We + ((size_t)(l * HID + hid)) * HID + h * DD;
            const float* ap = ae + (l * HH + h) * DD;
            float s = 0.f;
#pragma unroll 8
            for (int d = 0; d < DD; d++) s += wp[d] * ap[d];
            g_V[idx] = s;
        }
        return;
    }
    const float* src;
    int n0, k0, K, w = -1;
    if (b < 240) {
        const int b2 = b - 208;
        src = enc_w; K = IN_F;
        n0 = (b2 & 7) * 32;
        k0 = (b2 >> 3) * 32;
    } else {
        const int b3 = b - 240;
        w = b3 >> 6;
        src = (w < 3) ? (Wn + (size_t)w * HID * HID) : out_w;
        K = HID;
        const int b4 = b3 & 63;
        n0 = (b4 & 7) * 32;
        k0 = (b4 >> 3) * 32;
    }
    const int tx = tid & 31, ty = tid >> 5;
#pragma unroll
    for (int i = 0; i < 32; i += 8)
        t[ty + i][tx] = src[(size_t)(k0 + ty + i) * HID + n0 + tx];
    __syncthreads();
    const int Kh = K >> 1;
#pragma unroll
    for (int it = 0; it < 2; it++) {
        int j = tid + it * 256;
        int n = j >> 4, c = j & 15;
        float ve = t[2 * c][n], vo = t[2 * c + 1][n];
        size_t o = (size_t)(n0 + n) * Kh + (k0 >> 1) + c;
        if (w < 0) {
            uint32_t hi, lo;
            cvt_pair(ve, vo, hi, lo);
            g_BTh[o] = hi;
            g_BTl[o] = lo;
        } else {
            g_WF16[w * 32768 + o] = packh2(ve, vo);
        }
    }
}

// ---------------- fused front 2: hist + fold-U ----------------------------------
__global__ __launch_bounds__(256) void k_front2(const int* __restrict__ dst,
                                                const float* __restrict__ eenc_w,
                                                const float* __restrict__ eenc_b) {
    const int b = blockIdx.x;
    const int tid = threadIdx.x;
    if (b < 3125) {
        int i = b * 256 + tid;
        if (i < EE) atomicAdd(&g_cursor[dst[i]], 1);
    } else {
        int idx = (b - 3125) * 256 + tid;
        if (idx < LNUM * EIN_F * HH) {
            int h = idx & 3;
            int k = (idx >> 2) & 63;
            int l = idx >> 8;
            const float* wp = eenc_w + k * HID;
            float s = 0.f;
#pragma unroll 8
            for (int hid = 0; hid < HID; hid++) s += wp[hid] * g_V[(l * HID + hid) * HH + h];
            g_U[idx] = s;
        } else if (idx < LNUM * EIN_F * HH + LNUM * HH) {
            int j = idx - LNUM * EIN_F * HH;
            int l = j >> 2, h = j & 3;
            float s = 0.f;
            for (int hid = 0; hid < HID; hid++) s += eenc_b[hid] * g_V[(l * HID + hid) * HH + h];
            g_eebias[j] = s;
        }
    }
}

// ---------------- scan (also initializes cursor) --------------------------------
__global__ void k_scan() {
    __shared__ int sh[1024];
    const int t = threadIdx.x;
    const int chunk = (NN + 1023) / 1024;
    const int start = t * chunk;
    const int end = min(start + chunk, NN);
    int s = 0;
    for (int i = start; i < end; i++) s += g_cursor[i];
    sh[t] = s;
    __syncthreads();
    for (int o = 1; o < 1024; o <<= 1) {
        int v = (t >= o) ? sh[t - o] : 0;
        __syncthreads();
        sh[t] += v;
        __syncthreads();
    }
    int run = sh[t] - s;
    for (int i = start; i < end; i++) {
        int d = g_cursor[i];
        g_off[i] = run;
        g_cursor[i] = run;
        run += d;
    }
    if (t == 1023) g_off[NN] = sh[1023];
}

// ---------------- fused: scatter + ee GEMM --------------------------------------
__global__ __launch_bounds__(256) void k_scatter_ee(const int* __restrict__ src,
                                                    const int* __restrict__ dst,
                                                    const float* __restrict__ efeat) {
    __shared__ float fs[128 * 65];
    __shared__ float us[64 * 12];
    const int b = blockIdx.x;
    const int tid = threadIdx.x;
    if (b < 3125) {
        int i = b * 256 + tid;
        if (i < EE) {
            int p = atomicAdd(&g_cursor[dst[i]], 1);
            g_csr_src[p] = src[i];
            g_csr_eid[p] = i;
        }
    } else {
        const int e0 = (b - 3125) * 128;
        for (int i = tid; i < 128 * 64; i += 256) {
            int e = i >> 6, k = i & 63;
            fs[e * 65 + k] = efeat[(size_t)(e0 + e) * 64 + k];
        }
        for (int i = tid; i < LNUM * EIN_F * HH; i += 256) {
            int h = i & 3, k = (i >> 2) & 63, l = i >> 8;
            us[k * 12 + l * 4 + h] = g_U[i];
        }
        __syncthreads();
#pragma unroll
        for (int p0 = 0; p0 < 6; p0++) {
            int p = p0 * 256 + tid;
            int e = p & 127, out = p >> 7;
            const float* fp = &fs[e * 65];
            float acc = 0.f;
#pragma unroll
            for (int k = 0; k < 64; k++) acc += fp[k] * us[k * 12 + out];
            g_ee[(size_t)(e0 + e) * 12 + out] = acc + g_eebias[out];
        }
    }
}

// ---------------- bf16 3-split GEMM (enc only): fp32 C (+bias) ------------------
#define SST 20
#define BUFU 7680
__global__ __launch_bounds__(256, 2) void k_gemm_bf16(
    const float* __restrict__ A, const uint32_t* __restrict__ BTh,
    const uint32_t* __restrict__ BTl, const float* __restrict__ bias,
    float* __restrict__ C, int M, int K) {
    extern __shared__ uint32_t smu[];

    const int tid = threadIdx.x;
    const int wid = tid >> 5;
    const int lane = tid & 31;
    const int g = lane >> 2;
    const int tg = lane & 3;
    const int m0 = blockIdx.x * 128;
    const int col0 = blockIdx.y * 64;
    const int wm = wid >> 1;
    const int wn = wid & 1;
    const int Kh = K >> 1;
    const int nchunk = K >> 5;

    const int fAr = tid >> 3, fAc = (tid & 7) << 2;
    const int fBr = tid >> 2, fBq = (tid & 3) << 2;

    const uint32_t smem_base = smem_u32(smu);
    const int l15 = lane & 15;
    const uint32_t aRowOff = (uint32_t)(((wm * 32 + l15) * SST + ((lane >> 4) & 1) * 4) * 4);
    const int bm = lane >> 3, br = lane & 7;
    const uint32_t bX4Off = (uint32_t)(((wn * 32 + (bm >> 1) * 8 + br) * SST + (bm & 1) * 4) * 4);

    float acc[2][4][4];
#pragma unroll
    for (int i = 0; i < 2; i++)
#pragma unroll
        for (int j = 0; j < 4; j++)
#pragma unroll
            for (int q = 0; q < 4; q++) acc[i][j][q] = 0.f;

    float4 stA[4];
    uint4 stBh, stBl;

#define LOADG(cc) do {                                                        \
    const int kc0 = (cc) << 5;                                                \
    _Pragma("unroll")                                                         \
    for (int t = 0; t < 4; t++) {                                             \
        int gr = min(m0 + fAr + t * 32, M - 1);                               \
        stA[t] = *(const float4*)(A + (size_t)gr * K + kc0 + fAc);            \
    }                                                                         \
    {                                                                         \
        size_t o = (size_t)(col0 + fBr) * Kh + ((cc) << 4) + fBq;             \
        stBh = *(const uint4*)(BTh + o);                                      \
        stBl = *(const uint4*)(BTl + o);                                      \
    }                                                                         \
} while (0)

#define STOREB(buf) do {                                                      \
    uint32_t* bA = smu + (buf)*BUFU;                                          \
    _Pragma("unroll")                                                         \
    for (int t = 0; t < 4; t++) {                                             \
        float4 v = stA[t];                                                    \
        uint32_t h01, l01, h23, l23;                                          \
        cvt_pair(v.x, v.y, h01, l01);                                         \
        cvt_pair(v.z, v.w, h23, l23);                                         \
        int so = (fAr + t * 32) * SST + (fAc >> 1);                           \
        *(uint2*)(bA + so) = make_uint2(h01, h23);                            \
        *(uint2*)(bA + 2560 + so) = make_uint2(l01, l23);                     \
    }                                                                         \
    {                                                                         \
        int so = fBr * SST + fBq;                                             \
        *(uint4*)(bA + 5120 + so) = stBh;                                     \
        *(uint4*)(bA + 6400 + so) = stBl;                                     \
    }                                                                         \
} while (0)

    LOADG(0);
    STOREB(0);
    __syncthreads();

    for (int c = 0; c < nchunk; c++) {
        const int cur = c & 1;
        const bool more = (c + 1 < nchunk);
        if (more) LOADG(c + 1);

        const uint32_t bufB = smem_base + (uint32_t)(cur * BUFU * 4);
#pragma unroll
        for (int ks = 0; ks < 2; ks++) {
            uint32_t ah[2][4], al_[2][4], bh[4][2], bl[4][2];
            const uint32_t aH = bufB + aRowOff + ks * 32;
            const uint32_t bH = bufB + 5120 * 4 + bX4Off + ks * 32;
#pragma unroll
            for (int ma = 0; ma < 2; ma++) {
                ldsm_x4(ah[ma], aH + ma * (16 * SST * 4));
                ldsm_x4(al_[ma], aH + 2560 * 4 + ma * (16 * SST * 4));
            }
#pragma unroll
            for (int p = 0; p < 2; p++) {
                uint32_t bt[4];
                ldsm_x4(bt, bH + p * (16 * SST * 4));
                bh[2 * p][0] = bt[0]; bh[2 * p][1] = bt[1];
                bh[2 * p + 1][0] = bt[2]; bh[2 * p + 1][1] = bt[3];
                ldsm_x4(bt, bH + 1280 * 4 + p * (16 * SST * 4));
                bl[2 * p][0] = bt[0]; bl[2 * p][1] = bt[1];
                bl[2 * p + 1][0] = bt[2]; bl[2 * p + 1][1] = bt[3];
            }
#pragma unroll
            for (int ma = 0; ma < 2; ma++)
#pragma unroll
                for (int na = 0; na < 4; na++) mma_bf16(acc[ma][na], ah[ma], bh[na]);
#pragma unroll
            for (int ma = 0; ma < 2; ma++)
#pragma unroll
                for (int na = 0; na < 4; na++) mma_bf16(acc[ma][na], ah[ma], bl[na]);
#pragma unroll
            for (int ma = 0; ma < 2; ma++)
#pragma unroll
                for (int na = 0; na < 4; na++) mma_bf16(acc[ma][na], al_[ma], bh[na]);
        }
        if (more) {
            STOREB(1 - cur);
            __syncthreads();
        }
    }

#pragma unroll
    for (int ma = 0; ma < 2; ma++) {
        const int r0 = m0 + wm * 32 + ma * 16 + g;
        const int r1 = r0 + 8;
#pragma unroll
        for (int na = 0; na < 4; na++) {
            const int cc = col0 + wn * 32 + na * 8 + 2 * tg;
            float b0 = 0.f, b1 = 0.f;
            if (bias) { b0 = __ldg(bias + cc); b1 = __ldg(bias + cc + 1); }
            if (r0 < M) {
                float2 o = make_float2(acc[ma][na][0] + b0, acc[ma][na][1] + b1);
                *(float2*)(C + (size_t)r0 * 256 + cc) = o;
            }
            if (r1 < M) {
                float2 o = make_float2(acc[ma][na][2] + b0, acc[ma][na][3] + b1);
                *(float2*)(C + (size_t)r1 * 256 + cc) = o;
            }
        }
    }
#undef LOADG
#undef STOREB
}

// ---------------- fp16 single-term GEMM: feat mode (FEATH+el/er) or C mode ------
#define BUF16 3840   // u32/buffer: A 128*20=2560, B 64*20=1280
__global__ __launch_bounds__(256, 2) void k_gemm_f16(
    const float* __restrict__ A, const uint32_t* __restrict__ WF,
    const float* __restrict__ bias, float* __restrict__ C,
    int M, const float* __restrict__ alp, const float* __restrict__ arp) {
    extern __shared__ uint32_t smu[];
    const int K = HID;

    const int tid = threadIdx.x;
    const int wid = tid >> 5;
    const int lane = tid & 31;
    const int g = lane >> 2;
    const int tg = lane & 3;
    const int m0 = blockIdx.x * 128;
    const int col0 = blockIdx.y * 64;
    const int wm = wid >> 1;
    const int wn = wid & 1;
    const int Kh = K >> 1;
    const int nchunk = K >> 5;

    if (alp) {
        const int h = blockIdx.y;
        if (tid < 128) {
            int r = m0 + tid;
            if (r < M) g_el[r * 4 + h] = 0.f;
        } else {
            int r = m0 + tid - 128;
            if (r < M) g_er[r * 4 + h] = 0.f;
        }
    }

    const int fAr = tid >> 3, fAc = (tid & 7) << 2;
    const int fBr = tid >> 2, fBq = (tid & 3) << 2;

    const uint32_t smem_base = smem_u32(smu);
    const int l15 = lane & 15;
    const uint32_t aRowOff = (uint32_t)(((wm * 32 + l15) * SST + ((lane >> 4) & 1) * 4) * 4);
    const int bm = lane >> 3, br = lane & 7;
    const uint32_t bX4Off = (uint32_t)(((wn * 32 + (bm >> 1) * 8 + br) * SST + (bm & 1) * 4) * 4);

    float acc[2][4][4];
#pragma unroll
    for (int i = 0; i < 2; i++)
#pragma unroll
        for (int j = 0; j < 4; j++)
#pragma unroll
            for (int q = 0; q < 4; q++) acc[i][j][q] = 0.f;

    float4 stA[4];
    uint4 stB;

#define LOADG16(cc) do {                                                      \
    const int kc0 = (cc) << 5;                                                \
    _Pragma("unroll")                                                         \
    for (int t = 0; t < 4; t++) {                                             \
        int gr = min(m0 + fAr + t * 32, M - 1);                               \
        stA[t] = *(const float4*)(A + (size_t)gr * K + kc0 + fAc);            \
    }                                                                         \
    stB = *(const uint4*)(WF + (size_t)(col0 + fBr) * Kh + ((cc) << 4) + fBq);\
} while (0)

#define STOREB16(buf) do {                                                    \
    uint32_t* bA = smu + (buf)*BUF16;                                         \
    _Pragma("unroll")                                                         \
    for (int t = 0; t < 4; t++) {                                             \
        float4 v = stA[t];                                                    \
        int so = (fAr + t * 32) * SST + (fAc >> 1);                           \
        *(uint2*)(bA + so) = make_uint2(packh2(v.x, v.y), packh2(v.z, v.w));  \
    }                                                                         \
    *(uint4*)(bA + 2560 + fBr * SST + fBq) = stB;                             \
} while (0)

    LOADG16(0);
    STOREB16(0);
    __syncthreads();

    for (int c = 0; c < nchunk; c++) {
        const int cur = c & 1;
        const bool more = (c + 1 < nchunk);
        if (more) LOADG16(c + 1);

        const uint32_t bufB = smem_base + (uint32_t)(cur * BUF16 * 4);
#pragma unroll
        for (int ks = 0; ks < 2; ks++) {
            uint32_t ah[2][4], bh[4][2];
            const uint32_t aH = bufB + aRowOff + ks * 32;
            const uint32_t bH = bufB + 2560 * 4 + bX4Off + ks * 32;
#pragma unroll
            for (int ma = 0; ma < 2; ma++)
                ldsm_x4(ah[ma], aH + ma * (16 * SST * 4));
#pragma unroll
            for (int p = 0; p < 2; p++) {
                uint32_t bt[4];
                ldsm_x4(bt, bH + p * (16 * SST * 4));
                bh[2 * p][0] = bt[0]; bh[2 * p][1] = bt[1];
                bh[2 * p + 1][0] = bt[2]; bh[2 * p + 1][1] = bt[3];
            }
#pragma unroll
            for (int ma = 0; ma < 2; ma++)
#pragma unroll
                for (int na = 0; na < 4; na++) mma_f16(acc[ma][na], ah[ma], bh[na]);
        }
        if (more) {
            STOREB16(1 - cur);
            __syncthreads();
        }
    }

    if (C) {
        // fp32 C (+bias) epilogue (out GEMM)
#pragma unroll
        for (int ma = 0; ma < 2; ma++) {
            const int r0 = m0 + wm * 32 + ma * 16 + g;
            const int r1 = r0 + 8;
#pragma unroll
            for (int na = 0; na < 4; na++) {
                const int cc = col0 + wn * 32 + na * 8 + 2 * tg;
                float b0 = 0.f, b1 = 0.f;
                if (bias) { b0 = __ldg(bias + cc); b1 = __ldg(bias + cc + 1); }
                if (r0 < M) {
                    float2 o = make_float2(acc[ma][na][0] + b0, acc[ma][na][1] + b1);
                    *(float2*)(C + (size_t)r0 * 256 + cc) = o;
                }
                if (r1 < M) {
                    float2 o = make_float2(acc[ma][na][2] + b0, acc[ma][na][3] + b1);
                    *(float2*)(C + (size_t)r1 * 256 + cc) = o;
                }
            }
        }
        return;
    }

    // FEATH half2 epilogue
#pragma unroll
    for (int ma = 0; ma < 2; ma++) {
        const int r0 = m0 + wm * 32 + ma * 16 + g;
        const int r1 = r0 + 8;
#pragma unroll
        for (int na = 0; na < 4; na++) {
            const int cc = col0 + wn * 32 + na * 8 + 2 * tg;
            if (r0 < M)
                g_FEATH[(size_t)r0 * 128 + (cc >> 1)] = packh2(acc[ma][na][0], acc[ma][na][1]);
            if (r1 < M)
                g_FEATH[(size_t)r1 * 128 + (cc >> 1)] = packh2(acc[ma][na][2], acc[ma][na][3]);
        }
    }
    // fused el/er
    {
        const int h = blockIdx.y;
        float av0[4], av1[4], rv0[4], rv1[4];
#pragma unroll
        for (int na = 0; na < 4; na++) {
            const int d = wn * 32 + na * 8 + 2 * tg;
            av0[na] = __ldg(alp + h * DD + d);
            av1[na] = __ldg(alp + h * DD + d + 1);
            rv0[na] = __ldg(arp + h * DD + d);
            rv1[na] = __ldg(arp + h * DD + d + 1);
        }
#pragma unroll
        for (int ma = 0; ma < 2; ma++) {
            float pel0 = 0.f, pel1 = 0.f, per0 = 0.f, per1 = 0.f;
#pragma unroll
            for (int na = 0; na < 4; na++) {
                pel0 += acc[ma][na][0] * av0[na] + acc[ma][na][1] * av1[na];
                pel1 += acc[ma][na][2] * av0[na] + acc[ma][na][3] * av1[na];
                per0 += acc[ma][na][0] * rv0[na] + acc[ma][na][1] * rv1[na];
                per1 += acc[ma][na][2] * rv0[na] + acc[ma][na][3] * rv1[na];
            }
#pragma unroll
            for (int o = 1; o < 4; o <<= 1) {
                pel0 += __shfl_xor_sync(0xffffffffu, pel0, o);
                pel1 += __shfl_xor_sync(0xffffffffu, pel1, o);
                per0 += __shfl_xor_sync(0xffffffffu, per0, o);
                per1 += __shfl_xor_sync(0xffffffffu, per1, o);
            }
            if (tg == 0) {
                const int r0 = m0 + wm * 32 + ma * 16 + g;
                const int r1 = r0 + 8;
                if (r0 < M) {
                    atomicAdd(&g_el[r0 * 4 + h], pel0);
                    atomicAdd(&g_er[r0 * 4 + h], per0);
                }
                if (r1 < M) {
                    atomicAdd(&g_el[r1 * 4 + h], pel1);
                    atomicAdd(&g_er[r1 * 4 + h], per1);
                }
            }
        }
    }
#undef LOADG16
#undef STOREB16
}

// ---------------- per-dst-node: softmax + aggregate (half2 feat) + LN -----------
__device__ __forceinline__ float lrelu(float e) { return e > 0.f ? e : 0.2f * e; }

__global__ __launch_bounds__(256) void k_edge(int l,
                                              const float* __restrict__ ln_g,
                                              const float* __restrict__ ln_b) {
    const int lane = threadIdx.x & 31;
    const int n = blockIdx.x * 8 + (threadIdx.x >> 5);
    if (n >= NN) return;
    const int beg = g_off[n], end = g_off[n + 1];
    const float4 er4 = *(const float4*)&g_er[n * 4];

    float s0 = 0.f, s1 = 0.f, s2 = 0.f, s3 = 0.f;
    for (int i = beg + lane; i < end; i += 32) {
        const int s = g_csr_src[i];
        const int eid = g_csr_eid[i];
        const float4 el4 = *(const float4*)&g_el[s * 4];
        const float4 ee4 = *(const float4*)&g_ee[(size_t)eid * 12 + l * 4];
        float4 e;
        e.x = __expf(lrelu(el4.x + er4.x + ee4.x)); s0 += e.x;
        e.y = __expf(lrelu(el4.y + er4.y + ee4.y)); s1 += e.y;
        e.z = __expf(lrelu(el4.z + er4.z + ee4.z)); s2 += e.z;
        e.w = __expf(lrelu(el4.w + er4.w + ee4.w)); s3 += e.w;
        *(float4*)&g_alpha[(size_t)i * 4] = e;
    }
#pragma unroll
    for (int o = 16; o; o >>= 1) {
        s0 += __shfl_xor_sync(0xffffffffu, s0, o);
        s1 += __shfl_xor_sync(0xffffffffu, s1, o);
        s2 += __shfl_xor_sync(0xffffffffu, s2, o);
        s3 += __shfl_xor_sync(0xffffffffu, s3, o);
    }
    __syncwarp();
    const int myhead = lane >> 3;
    const float rs_my = (myhead == 0) ? 1.f / s0 : (myhead == 1) ? 1.f / s1
                      : (myhead == 2) ? 1.f / s2 : 1.f / s3;

    float a0 = 0.f, a1 = 0.f, a2 = 0.f, a3 = 0.f, a4 = 0.f, a5 = 0.f, a6 = 0.f, a7 = 0.f;
    int i = beg;
    for (; i + 4 <= end; i += 4) {
        float aw[4];
        const uint4* fr[4];
#pragma unroll
        for (int u = 0; u < 4; u++) {
            const int sx = g_csr_src[i + u];
            const float4 alv = *(const float4*)&g_alpha[(size_t)(i + u) * 4];
            aw[u] = ((myhead == 0) ? alv.x : (myhead == 1) ? alv.y
                    : (myhead == 2) ? alv.z : alv.w) * rs_my;
            fr[u] = (const uint4*)(g_FEATH + (size_t)sx * 128 + lane * 4);
        }
        uint4 fv[4];
#pragma unroll
        for (int u = 0; u < 4; u++) fv[u] = __ldg(fr[u]);
#pragma unroll
        for (int u = 0; u < 4; u++) {
            const float a = aw[u];
            float2 p0 = __half22float2(*reinterpret_cast<__half2*>(&fv[u].x));
            float2 p1 = __half22float2(*reinterpret_cast<__half2*>(&fv[u].y));
            float2 p2 = __half22float2(*reinterpret_cast<__half2*>(&fv[u].z));
            float2 p3 = __half22float2(*reinterpret_cast<__half2*>(&fv[u].w));
            a0 += a * p0.x; a1 += a * p0.y; a2 += a * p1.x; a3 += a * p1.y;
            a4 += a * p2.x; a5 += a * p2.y; a6 += a * p3.x; a7 += a * p3.y;
        }
    }
    for (; i < end; i++) {
        const int sA = g_csr_src[i];
        const float4 alv = *(const float4*)&g_alpha[(size_t)i * 4];
        const float a = ((myhead == 0) ? alv.x : (myhead == 1) ? alv.y
                        : (myhead == 2) ? alv.z : alv.w) * rs_my;
        uint4 fv = __ldg((const uint4*)(g_FEATH + (size_t)sA * 128 + lane * 4));
        float2 p0 = __half22float2(*reinterpret_cast<__half2*>(&fv.x));
        float2 p1 = __half22float2(*reinterpret_cast<__half2*>(&fv.y));
        float2 p2 = __half22float2(*reinterpret_cast<__half2*>(&fv.z));
        float2 p3 = __half22float2(*reinterpret_cast<__half2*>(&fv.w));
        a0 += a * p0.x; a1 += a * p0.y; a2 += a * p1.x; a3 += a * p1.y;
        a4 += a * p2.x; a5 += a * p2.y; a6 += a * p3.x; a7 += a * p3.y;
    }

    const float4 r0 = *(const float4*)(g_X + (size_t)n * HID + lane * 8);
    const float4 r1 = *(const float4*)(g_X + (size_t)n * HID + lane * 8 + 4);
    float y[8];
    y[0] = fmaxf(a0, 0.f) + r0.x; y[1] = fmaxf(a1, 0.f) + r0.y;
    y[2] = fmaxf(a2, 0.f) + r0.z; y[3] = fmaxf(a3, 0.f) + r0.w;
    y[4] = fmaxf(a4, 0.f) + r1.x; y[5] = fmaxf(a5, 0.f) + r1.y;
    y[6] = fmaxf(a6, 0.f) + r1.z; y[7] = fmaxf(a7, 0.f) + r1.w;
    float sum = 0.f;
#pragma unroll
    for (int j = 0; j < 8; j++) sum += y[j];
#pragma unroll
    for (int o = 16; o; o >>= 1) sum += __shfl_xor_sync(0xffffffffu, sum, o);
    const float mu = sum * (1.f / 256.f);
    float vs = 0.f;
#pragma unroll
    for (int j = 0; j < 8; j++) { float d = y[j] - mu; vs += d * d; }
#pragma unroll
    for (int o = 16; o; o >>= 1) vs += __shfl_xor_sync(0xffffffffu, vs, o);
    const float rstd = rsqrtf(vs * (1.f / 256.f) + 1e-5f);
    const float* gp = ln_g + lane * 8;
    const float* bp = ln_b + lane * 8;
    float4 o0, o1;
    o0.x = (y[0] - mu) * rstd * gp[0] + bp[0];
    o0.y = (y[1] - mu) * rstd * gp[1] + bp[1];
    o0.z = (y[2] - mu) * rstd * gp[2] + bp[2];
    o0.w = (y[3] - mu) * rstd * gp[3] + bp[3];
    o1.x = (y[4] - mu) * rstd * gp[4] + bp[4];
    o1.y = (y[5] - mu) * rstd * gp[5] + bp[5];
    o1.z = (y[6] - mu) * rstd * gp[6] + bp[6];
    o1.w = (y[7] - mu) * rstd * gp[7] + bp[7];
    *(float4*)(g_X + (size_t)n * HID + lane * 8) = o0;
    *(float4*)(g_X + (size_t)n * HID + lane * 8 + 4) = o1;
}

// ---------------- launch ----------------
extern "C" void kernel_launch(void* const* d_in, const int* in_sizes, int n_in,
                              void* d_out, int out_size) {
    const float* h      = (const float*)d_in[0];
    const float* efeat  = (const float*)d_in[1];
    const int*   src    = (const int*)d_in[2];
    const int*   dst    = (const int*)d_in[3];
    const float* enc_w  = (const float*)d_in[4];
    const float* enc_b  = (const float*)d_in[5];
    const float* eenc_w = (const float*)d_in[6];
    const float* eenc_b = (const float*)d_in[7];
    const float* Wn     = (const float*)d_in[8];
    const float* We     = (const float*)d_in[9];
    const float* al     = (const float*)d_in[10];
    const float* ar     = (const float*)d_in[11];
    const float* ae     = (const float*)d_in[12];
    const float* ln_g   = (const float*)d_in[13];
    const float* ln_b   = (const float*)d_in[14];
    const float* out_w  = (const float*)d_in[15];
    const float* out_b  = (const float*)d_in[16];
    float* out = (float*)d_out;

    float* X;
    uint32_t *BTh, *BTl, *WF;
    cudaGetSymbolAddress((void**)&X, g_X);
    cudaGetSymbolAddress((void**)&BTh, g_BTh);
    cudaGetSymbolAddress((void**)&BTl, g_BTl);
    cudaGetSymbolAddress((void**)&WF, g_WF16);

    const int DSM = 2 * BUFU * 4;
    const int DSM16 = 2 * BUF16 * 4;
    cudaFuncSetAttribute(k_gemm_bf16, cudaFuncAttributeMaxDynamicSharedMemorySize, DSM);
    cudaFuncSetAttribute(k_gemm_f16, cudaFuncAttributeMaxDynamicSharedMemorySize, DSM16);
    const int MTILES = divup(NN, 128);
    const dim3 ggrid(MTILES, 4);

    k_front1<<<496, 256>>>(We, ae, enc_w, Wn, out_w);                    // 0
    k_front2<<<3129, 256>>>(dst, eenc_w, eenc_b);                        // 1
    k_scan<<<1, 1024>>>();                                               // 2
    k_gemm_bf16<<<ggrid, 256, DSM>>>(h, BTh, BTl, enc_b, X, NN, IN_F);   // 3 <- ncu
    k_scatter_ee<<<3125 + EE / 128, 256>>>(src, dst, efeat);             // 4

    for (int l = 0; l < LNUM; l++) {
        k_gemm_f16<<<ggrid, 256, DSM16>>>(X, WF + l * 32768, nullptr, nullptr, NN,
                                          al + l * HH * DD, ar + l * HH * DD);
        k_edge<<<divup(NN, 8), 256>>>(l, ln_g + l * HID, ln_b + l * HID);
    }

    k_gemm_f16<<<ggrid, 256, DSM16>>>(X, WF + 3 * 32768, out_b, out, NN,
                                      nullptr, nullptr);
}